// round 13
// baseline (speedup 1.0000x reference)
#include <cuda_runtime.h>
#include <cuda_fp16.h>
#include <cstdint>
#include <cmath>

// ---------------------------------------------------------------------------
// GPT-OSS attention block on sm_100 (legacy mma.sync path).
// Round 13: W_o transpose merged into the QKV GEMM launch (fills the wave-2
// scheduling tail with independent DRAM-bound work); attention moves to
// 128-query CTAs (33% less KV staging). All arithmetic bit-identical to R12.
// ---------------------------------------------------------------------------

#define T_LEN      1536
#define HIDDEN     2880
#define N_HEADS    64
#define N_KV       8
#define HEAD_DIM   64
#define WINDOW     128
#define Q_SIZE     4096
#define KV_SIZE    512
#define QKV_COLS   5120
#define O_NPAD     2944
#define ATT_SCALE  0.125f

// ---------------- scratch ---------------------------------------------------
__device__ __align__(256) float  g_qkv  [(size_t)T_LEN * QKV_COLS];
__device__ __align__(256) __half g_v16  [(size_t)T_LEN * KV_SIZE];
__device__ __align__(256) __half g_h_hi [(size_t)T_LEN * HIDDEN];
__device__ __align__(256) __half g_wq_hi[(size_t)QKV_COLS * HIDDEN];
__device__ __align__(256) __half g_wo_hi[(size_t)O_NPAD * Q_SIZE];
__device__ __align__(256) __half g_a_hi [(size_t)T_LEN * Q_SIZE];
__device__ __align__(256) float  g_rcos [(size_t)T_LEN * 32];
__device__ __align__(256) float  g_rsin [(size_t)T_LEN * 32];

// ---------------- helpers ---------------------------------------------------
static __device__ __forceinline__ uint32_t smem_u32(const void* p) {
    uint32_t a;
    asm("{ .reg .u64 t; cvta.to.shared.u64 t, %1; cvt.u32.u64 %0, t; }"
        : "=r"(a) : "l"(p));
    return a;
}

#define CP_ASYNC16(dst, src) \
    asm volatile("cp.async.cg.shared.global [%0], [%1], 16;" :: "r"(dst), "l"(src))
#define CP_COMMIT() asm volatile("cp.async.commit_group;")
#define CP_WAIT1()  asm volatile("cp.async.wait_group 1;")
#define CP_WAIT0()  asm volatile("cp.async.wait_group 0;")

static __device__ __forceinline__ void ldsm4(uint32_t* r, uint32_t addr) {
    asm volatile("ldmatrix.sync.aligned.m8n8.x4.shared.b16 {%0,%1,%2,%3}, [%4];"
                 : "=r"(r[0]), "=r"(r[1]), "=r"(r[2]), "=r"(r[3]) : "r"(addr));
}

static __device__ __forceinline__ void ldsm4t(uint32_t* r, uint32_t addr) {
    asm volatile("ldmatrix.sync.aligned.m8n8.x4.trans.shared.b16 {%0,%1,%2,%3}, [%4];"
                 : "=r"(r[0]), "=r"(r[1]), "=r"(r[2]), "=r"(r[3]) : "r"(addr));
}

static __device__ __forceinline__ void mma16816(float* d, const uint32_t* a,
                                                uint32_t b0, uint32_t b1) {
    asm volatile("mma.sync.aligned.m16n8k16.row.col.f32.f16.f16.f32 "
                 "{%0,%1,%2,%3}, {%4,%5,%6,%7}, {%8,%9}, {%0,%1,%2,%3};"
                 : "+f"(d[0]), "+f"(d[1]), "+f"(d[2]), "+f"(d[3])
                 : "r"(a[0]), "r"(a[1]), "r"(a[2]), "r"(a[3]), "r"(b0), "r"(b1));
}

// ---------------------------------------------------------------------------
// Shared GEMM tile body (identical math/schedule to R12).
// ---------------------------------------------------------------------------
#define GS           3
#define TILE_BYTES   16384
#define STAGE_BYTES  (2 * TILE_BYTES)
#define GEMM_DSMEM   (GS * STAGE_BYTES + 1024)
#define V_COL0       4608

static __device__ __forceinline__ void load_chunk(
    uint32_t st,
    const __half* __restrict__ Ah, const __half* __restrict__ Bh,
    int m0, int n0, int kk, int K, int tid)
{
    #pragma unroll
    for (int i = 0; i < 4; i++) {
        int ch  = tid + (i << 8);
        int rw  = ch >> 3;
        int c16 = ch & 7;
        uint32_t off = (uint32_t)(rw << 7) + (uint32_t)(c16 << 4);
        uint32_t sw  = off ^ ((off >> 3) & 0x70);
        const char* sa = (const char*)(Ah + (size_t)(m0 + rw) * K + kk) + (c16 << 4);
        const char* sb = (const char*)(Bh + (size_t)(n0 + rw) * K + kk) + (c16 << 4);
        CP_ASYNC16(st + sw,              sa);
        CP_ASYNC16(st + TILE_BYTES + sw, sb);
    }
}

static __device__ __forceinline__ void gemm_tile_body(
    char* dynsmem, int m0, int n0,
    const __half* __restrict__ A_hi, const __half* __restrict__ B_hi,
    const float* __restrict__ bias, float* __restrict__ C,
    __half* __restrict__ v16, int Nreal, int K)
{
    const uint32_t tile0 = (smem_u32(dynsmem) + 1023u) & ~1023u;

    const int tid  = threadIdx.x;
    const int wid  = tid >> 5;
    const int lane = tid & 31;
    const int wm   = (wid & 1) * 64;
    const int wn   = (wid >> 1) * 32;

    const int r7 = lane & 7;
    const int q  = lane >> 3;
    const int rA = ((q & 1) << 3) + r7;
    const int cq = q >> 1;

    const int nch = K >> 6;

    float acc[4][4][4];
    #pragma unroll
    for (int a = 0; a < 4; a++)
        #pragma unroll
        for (int b = 0; b < 4; b++)
            #pragma unroll
            for (int c = 0; c < 4; c++) acc[a][b][c] = 0.0f;

    #pragma unroll
    for (int c = 0; c < GS - 1; c++) {
        load_chunk(tile0 + c * STAGE_BYTES, A_hi, B_hi, m0, n0, c << 6, K, tid);
        CP_COMMIT();
    }

    int stage_c = 0, stage_p = GS - 1;
    for (int c = 0; c < nch; c++) {
        CP_WAIT1();
        __syncthreads();

        if (c + GS - 1 < nch)
            load_chunk(tile0 + stage_p * STAGE_BYTES, A_hi, B_hi,
                       m0, n0, (c + GS - 1) << 6, K, tid);
        CP_COMMIT();
        if (++stage_p == GS) stage_p = 0;

        const uint32_t aB = tile0 + stage_c * STAGE_BYTES;
        const uint32_t bB = aB + TILE_BYTES;
        if (++stage_c == GS) stage_c = 0;

        #pragma unroll
        for (int ks = 0; ks < 4; ks++) {
            uint32_t afr[4][4], bfr[2][4];
            const uint32_t chsw = (uint32_t)(((ks * 2 + cq) ^ r7) << 4);
            #pragma unroll
            for (int mt = 0; mt < 4; mt++)
                ldsm4(afr[mt], aB + (uint32_t)((wm + mt * 16 + rA) << 7) + chsw);
            #pragma unroll
            for (int ng = 0; ng < 2; ng++)
                ldsm4(bfr[ng], bB + (uint32_t)((wn + ng * 16 + rA) << 7) + chsw);

            #pragma unroll
            for (int mt = 0; mt < 4; mt++)
                #pragma unroll
                for (int nt = 0; nt < 4; nt++) {
                    const int ng = nt >> 1, hl = nt & 1;
                    mma16816(acc[mt][nt], afr[mt], bfr[ng][hl], bfr[ng][hl + 2]);
                }
        }
    }

    const int trow = lane >> 2;
    const int tcol = (lane & 3) * 2;
    const bool vtile = (v16 != nullptr) && (n0 >= V_COL0);
    #pragma unroll
    for (int mt = 0; mt < 4; mt++) {
        #pragma unroll
        for (int nt = 0; nt < 4; nt++) {
            const int col = n0 + wn + nt * 8 + tcol;
            if (col < Nreal) {
                const float2 b2 = *reinterpret_cast<const float2*>(bias + col);
                const int row0 = m0 + wm + mt * 16 + trow;
                float2 o0, o1;
                o0.x = acc[mt][nt][0] + b2.x;  o0.y = acc[mt][nt][1] + b2.y;
                o1.x = acc[mt][nt][2] + b2.x;  o1.y = acc[mt][nt][3] + b2.y;
                if (vtile) {
                    const int vc = col - V_COL0;
                    *reinterpret_cast<__half2*>(v16 + (size_t)row0 * KV_SIZE + vc) =
                        __floats2half2_rn(o0.x, o0.y);
                    *reinterpret_cast<__half2*>(v16 + (size_t)(row0 + 8) * KV_SIZE + vc) =
                        __floats2half2_rn(o1.x, o1.y);
                } else {
                    *reinterpret_cast<float2*>(C + (size_t)row0 * Nreal + col)       = o0;
                    *reinterpret_cast<float2*>(C + (size_t)(row0 + 8) * Nreal + col) = o1;
                }
            }
        }
    }
}

// ---------------------------------------------------------------------------
// Weight transpose tile (64k x 32n), shared by preproc and the fused kernel.
// ---------------------------------------------------------------------------
static __device__ __forceinline__ void wtile_body(
    float (*tile)[33], int b, int nx, int K, int N,
    const float* __restrict__ W, __half* __restrict__ dst)
{
    const int tid = threadIdx.x;
    const int n0 = (b % nx) * 32;
    const int k0 = (b / nx) * 64;

    #pragma unroll
    for (int i = 0; i < 2; i++) {
        const int id = tid + (i << 8);
        const int kr = id >> 3;
        const int c4 = (id & 7) * 4;
        const int n  = n0 + c4;
        float4 v = make_float4(0.f, 0.f, 0.f, 0.f);
        if (n < N)
            v = *reinterpret_cast<const float4*>(W + (size_t)(k0 + kr) * N + n);
        tile[kr][c4 + 0] = v.x;  tile[kr][c4 + 1] = v.y;
        tile[kr][c4 + 2] = v.z;  tile[kr][c4 + 3] = v.w;
    }
    __syncthreads();

    const int nr = tid >> 3;
    const int kc = (tid & 7) * 8;
    __half hb[8];
    #pragma unroll
    for (int x = 0; x < 8; x++)
        hb[x] = __float2half_rn(tile[kc + x][nr]);
    *reinterpret_cast<uint4*>(dst + (size_t)(n0 + nr) * K + k0 + kc) =
        *reinterpret_cast<const uint4*>(hb);
}

// ---------------------------------------------------------------------------
// Fused QKV GEMM + W_o transpose (tail-fill) kernel. 1D grid:
//   [0, 480)            : QKV GEMM tiles (40 n x 12 m)
//   [480, 480 + 5888)   : W_o transpose tiles (92 n x 64 k)
// ---------------------------------------------------------------------------
#define QKV_TILES     480
#define WO_TILES      5888
#define QKV_FUSED_GRID (QKV_TILES + WO_TILES)

__global__ __launch_bounds__(256, 2)
void qkv_fused_kernel(const __half* __restrict__ h_hi,
                      const __half* __restrict__ wq_hi,
                      const float* __restrict__ b_qkv,
                      float* __restrict__ qkv,
                      __half* __restrict__ v16,
                      const float* __restrict__ W_o,
                      __half* __restrict__ wo_hi)
{
    extern __shared__ char dynsmem[];
    const int bid = blockIdx.x;
    if (bid < QKV_TILES) {
        gemm_tile_body(dynsmem, (bid / 40) * 128, (bid % 40) * 128,
                       h_hi, wq_hi, b_qkv, qkv, v16, QKV_COLS, HIDDEN);
    } else {
        wtile_body(reinterpret_cast<float(*)[33]>(dynsmem),
                   bid - QKV_TILES, O_NPAD / 32, Q_SIZE, HIDDEN, W_o, wo_hi);
    }
}

// ---------------------------------------------------------------------------
// O projection GEMM (2D grid, fp32 output only).
// ---------------------------------------------------------------------------
__global__ __launch_bounds__(256, 2)
void ogemm_kernel(const __half* __restrict__ A_hi,
                  const __half* __restrict__ B_hi,
                  const float* __restrict__ bias, float* __restrict__ C,
                  int Nreal, int K)
{
    extern __shared__ char dynsmem[];
    gemm_tile_body(dynsmem, blockIdx.y * 128, blockIdx.x * 128,
                   A_hi, B_hi, bias, C, nullptr, Nreal, K);
}

// ---------------------------------------------------------------------------
// Preprocessing: hidden->fp16 (4320), W_qkv transpose (7200), rope table (192)
// ---------------------------------------------------------------------------
#define PP_SPLIT_BLOCKS  4320
#define PP_THI1_BLOCKS   7200
#define PP_ROPE_BLOCKS   192
#define PP_TOTAL_BLOCKS  (PP_SPLIT_BLOCKS + PP_THI1_BLOCKS + PP_ROPE_BLOCKS)

__global__ __launch_bounds__(256)
void preproc_kernel(const float* __restrict__ hidden,
                    const float* __restrict__ W_qkv,
                    const int* __restrict__ positions,
                    __half* __restrict__ h_hi,
                    __half* __restrict__ wq_hi,
                    float* __restrict__ rcos,
                    float* __restrict__ rsin)
{
    __shared__ float tile[64][33];
    const int bid = blockIdx.x;
    const int tid = threadIdx.x;

    if (bid < PP_SPLIT_BLOCKS) {
        const int i = bid * 256 + tid;
        float4 v = reinterpret_cast<const float4*>(hidden)[i];
        reinterpret_cast<__half2*>(h_hi)[2 * i + 0] =
            __halves2half2(__float2half_rn(v.x), __float2half_rn(v.y));
        reinterpret_cast<__half2*>(h_hi)[2 * i + 1] =
            __halves2half2(__float2half_rn(v.z), __float2half_rn(v.w));
        return;
    }

    if (bid < PP_SPLIT_BLOCKS + PP_THI1_BLOCKS) {
        wtile_body(tile, bid - PP_SPLIT_BLOCKS, QKV_COLS / 32,
                   HIDDEN, QKV_COLS, W_qkv, wq_hi);
        return;
    }

    // rope table
    {
        const int i = (bid - PP_SPLIT_BLOCKS - PP_THI1_BLOCKS) * 256 + tid;
        if (i >= T_LEN * 32) return;
        const int d = i & 31;
        const int t = i >> 5;

        const float p = (float)positions[t];
        const float lnB   = logf(150000.0f);
        const float freq  = expf(lnB * ((float)d / 32.0f));
        const float conc  = 0.1f * logf(32.0f) + 1.0f;
        const float twoPi = 6.283185307179586f;
        const float low   = 32.0f * logf(4096.0f / (32.0f * twoPi)) / lnB;
        const float high  = 32.0f * logf(4096.0f / (1.0f  * twoPi)) / lnB;
        float ramp = ((float)d - low) / (high - low);
        ramp = fminf(fmaxf(ramp, 0.0f), 1.0f);
        const float inv_freq = ramp / (32.0f * freq) + (1.0f - ramp) / freq;

        const float ang = p * inv_freq;
        rcos[i] = cosf(ang) * conc;
        rsin[i] = sinf(ang) * conc;
    }
}

// ---------------------------------------------------------------------------
// Tensor-core flash attention, 128-query CTAs (256 KV rows staged once).
// Same per-query arithmetic order as R12 -> bit-identical output.
// ---------------------------------------------------------------------------
#define AROWS       256
#define ATTN_DSMEM  (32768 + 32768 + 16384)   // K + V + Q = 81920

__global__ __launch_bounds__(256, 2)
void attn_mma_kernel(const float* __restrict__ qkv,
                     const __half* __restrict__ v16,
                     const float* __restrict__ sinks,
                     const float* __restrict__ rcos,
                     const float* __restrict__ rsin,
                     __half* __restrict__ out_hi)
{
    extern __shared__ char asmem[];
    const uint32_t sbase = smem_u32(asmem);
    const uint32_t Ks = sbase;
    const uint32_t Vs = sbase + 32768;

    const int tid  = threadIdx.x;
    const int warp = tid >> 5;
    const int lane = tid & 31;
    const int i0   = blockIdx.x * 128;
    const int kv   = blockIdx.y;
    const int h    = kv * 8 + warp;
    const uint32_t Qs = sbase + 65536 + warp * 2048;

    // ---- V staging via cp.async (rows are 128B of fp16) ----
    for (int idx = tid; idx < AROWS * 8; idx += 256) {
        const int r = idx >> 3, c16 = idx & 7;
        const int j = i0 - 128 + r;
        const uint32_t off = (uint32_t)(r * 128) + ((uint32_t)(c16 ^ (r & 7)) << 4);
        if (j >= 0) {
            CP_ASYNC16(Vs + off,
                       (const char*)(v16 + (size_t)j * KV_SIZE + kv * 64) + (c16 << 4));
        } else {
            *reinterpret_cast<uint4*>(asmem + 32768 + off) = make_uint4(0u, 0u, 0u, 0u);
        }
    }
    CP_COMMIT();

    // ---- K staging with RoPE ----
    for (int idx = tid; idx < AROWS * 16; idx += 256) {
        const int r = idx >> 4, d2 = idx & 15;
        const int j = i0 - 128 + r;
        float2 y1 = make_float2(0.f, 0.f), y2 = make_float2(0.f, 0.f);
        if (j >= 0) {
            const float* src = qkv + (size_t)j * QKV_COLS + Q_SIZE + kv * 64;
            const float2 x1 = *reinterpret_cast<const float2*>(src + 2 * d2);
            const float2 x2 = *reinterpret_cast<const float2*>(src + 2 * d2 + 32);
            const float2 cc = *reinterpret_cast<const float2*>(rcos + j * 32 + 2 * d2);
            const float2 ss = *reinterpret_cast<const float2*>(rsin + j * 32 + 2 * d2);
            y1.x = x1.x * cc.x - x2.x * ss.x;  y1.y = x1.y * cc.y - x2.y * ss.y;
            y2.x = x2.x * cc.x + x1.x * ss.x;  y2.y = x2.y * cc.y + x1.y * ss.y;
        }
        const int d2b = d2 + 16;
        const uint32_t sw1 = (uint32_t)(r * 128) +
                             ((uint32_t)((d2 >> 2) ^ (r & 7)) << 4) + (d2 & 3) * 4;
        const uint32_t sw2 = (uint32_t)(r * 128) +
                             ((uint32_t)((d2b >> 2) ^ (r & 7)) << 4) + (d2b & 3) * 4;
        *reinterpret_cast<__half2*>(asmem + sw1) = __floats2half2_rn(y1.x, y1.y);
        *reinterpret_cast<__half2*>(asmem + sw2) = __floats2half2_rn(y2.x, y2.y);
    }
    CP_WAIT0();
    __syncthreads();

    const float snk = sinks[h];
    const int r7 = lane & 7;
    const int qq = lane >> 3;
    const int rA = ((qq & 1) << 3) + r7;
    const int cq = qq >> 1;
    const int vrow_l = (lane & 7) + ((lane >> 4) << 3);
    const int vnsel  = (lane >> 3) & 1;

    for (int mt = 0; mt < 8; mt++) {
        const int i_base = i0 + mt * 16;

        __syncwarp();
        for (int e = lane; e < 256; e += 32) {
            const int r = e >> 4, d2 = e & 15;
            const int t = i_base + r;
            const float* src = qkv + (size_t)t * QKV_COLS + h * 64;
            const float2 x1 = *reinterpret_cast<const float2*>(src + 2 * d2);
            const float2 x2 = *reinterpret_cast<const float2*>(src + 2 * d2 + 32);
            const float2 cc = *reinterpret_cast<const float2*>(rcos + t * 32 + 2 * d2);
            const float2 ss = *reinterpret_cast<const float2*>(rsin + t * 32 + 2 * d2);
            float2 y1, y2;
            y1.x = x1.x * cc.x - x2.x * ss.x;  y1.y = x1.y * cc.y - x2.y * ss.y;
            y2.x = x2.x * cc.x + x1.x * ss.x;  y2.y = x2.y * cc.y + x1.y * ss.y;
            const int d2b = d2 + 16;
            const uint32_t sw1 = (uint32_t)(r * 128) +
                                 ((uint32_t)((d2 >> 2) ^ (r & 7)) << 4) + (d2 & 3) * 4;
            const uint32_t sw2 = (uint32_t)(r * 128) +
                                 ((uint32_t)((d2b >> 2) ^ (r & 7)) << 4) + (d2b & 3) * 4;
            *reinterpret_cast<__half2*>(asmem + 65536 + warp * 2048 + sw1) =
                __floats2half2_rn(y1.x, y1.y);
            *reinterpret_cast<__half2*>(asmem + 65536 + warp * 2048 + sw2) =
                __floats2half2_rn(y2.x, y2.y);
        }
        __syncwarp();

        uint32_t aQ[4][4];
        #pragma unroll
        for (int ks = 0; ks < 4; ks++)
            ldsm4(aQ[ks], Qs + (uint32_t)(rA * 128) +
                          ((uint32_t)(((2 * ks + cq) ^ r7)) << 4));

        float m0 = snk, m1 = snk, l0 = 0.f, l1 = 0.f;
        float ofr[8][4];
        #pragma unroll
        for (int dn = 0; dn < 8; dn++)
            #pragma unroll
            for (int c = 0; c < 4; c++) ofr[dn][c] = 0.f;

        const int b_lo = mt >> 1;
        for (int bb = 0; bb < 5; bb++) {
            const int b = b_lo + bb;

            float sf[4][4];
            #pragma unroll
            for (int nt = 0; nt < 4; nt++)
                #pragma unroll
                for (int c = 0; c < 4; c++) sf[nt][c] = 0.f;

            #pragma unroll
            for (int ks = 0; ks < 4; ks++) {
                uint32_t bk0[4], bk1[4];
                const uint32_t chsw = (uint32_t)(((2 * ks + cq) ^ r7)) << 4;
                ldsm4(bk0, Ks + (uint32_t)((32 * b + rA) * 128) + chsw);
                ldsm4(bk1, Ks + (uint32_t)((32 * b + 16 + rA) * 128) + chsw);
                mma16816(sf[0], aQ[ks], bk0[0], bk0[2]);
                mma16816(sf[1], aQ[ks], bk0[1], bk0[3]);
                mma16816(sf[2], aQ[ks], bk1[0], bk1[2]);
                mma16816(sf[3], aQ[ks], bk1[1], bk1[3]);
            }

            const int jb  = i0 - 128 + 32 * b;
            const int ir0 = i_base + (lane >> 2);
            const int ir1 = ir0 + 8;
            float bm0 = -1e30f, bm1 = -1e30f;
            #pragma unroll
            for (int nt = 0; nt < 4; nt++) {
                const int jc = jb + nt * 8 + 2 * (lane & 3);
                #pragma unroll
                for (int c = 0; c < 2; c++) {
                    const int j = jc + c;
                    const float s0 = sf[nt][c] * ATT_SCALE;
                    const float s1 = sf[nt][c + 2] * ATT_SCALE;
                    const bool ok0 = (j >= 0) && (j <= ir0) && (ir0 - j < 128);
                    const bool ok1 = (j >= 0) && (j <= ir1) && (ir1 - j < 128);
                    sf[nt][c]     = ok0 ? s0 : -1e30f;
                    sf[nt][c + 2] = ok1 ? s1 : -1e30f;
                    bm0 = fmaxf(bm0, sf[nt][c]);
                    bm1 = fmaxf(bm1, sf[nt][c + 2]);
                }
            }
            bm0 = fmaxf(bm0, __shfl_xor_sync(0xFFFFFFFFu, bm0, 1));
            bm0 = fmaxf(bm0, __shfl_xor_sync(0xFFFFFFFFu, bm0, 2));
            bm1 = fmaxf(bm1, __shfl_xor_sync(0xFFFFFFFFu, bm1, 1));
            bm1 = fmaxf(bm1, __shfl_xor_sync(0xFFFFFFFFu, bm1, 2));

            const float nm0 = fmaxf(m0, bm0), nm1 = fmaxf(m1, bm1);
            const float sc0 = __expf(m0 - nm0), sc1 = __expf(m1 - nm1);
            m0 = nm0; m1 = nm1;
            l0 *= sc0; l1 *= sc1;
            #pragma unroll
            for (int dn = 0; dn < 8; dn++) {
                ofr[dn][0] *= sc0; ofr[dn][1] *= sc0;
                ofr[dn][2] *= sc1; ofr[dn][3] *= sc1;
            }

            uint32_t P01[4], P23[4];
            #pragma unroll
            for (int nt = 0; nt < 4; nt++) {
                const float p0 = __expf(sf[nt][0] - m0);
                const float p1 = __expf(sf[nt][1] - m0);
                const float p2 = __expf(sf[nt][2] - m1);
                const float p3 = __expf(sf[nt][3] - m1);
                l0 += p0 + p1;  l1 += p2 + p3;
                const __half2 h01 = __floats2half2_rn(p0, p1);
                const __half2 h23 = __floats2half2_rn(p2, p3);
                P01[nt] = *reinterpret_cast<const uint32_t*>(&h01);
                P23[nt] = *reinterpret_cast<const uint32_t*>(&h23);
            }

            #pragma unroll
            for (int kt = 0; kt < 2; kt++) {
                uint32_t aP[4] = {P01[2 * kt], P23[2 * kt],
                                  P01[2 * kt + 1], P23[2 * kt + 1]};
                const int vr = 32 * b + 16 * kt + vrow_l;
                #pragma unroll
                for (int dp = 0; dp < 4; dp++) {
                    uint32_t bv[4];
                    ldsm4t(bv, Vs + (uint32_t)(vr * 128) +
                               ((uint32_t)(((2 * dp + vnsel) ^ (vr & 7))) << 4));
                    mma16816(ofr[2 * dp],     aP, bv[0], bv[2]);
                    mma16816(ofr[2 * dp + 1], aP, bv[1], bv[3]);
                }
            }
        }

        l0 += __shfl_xor_sync(0xFFFFFFFFu, l0, 1);
        l0 += __shfl_xor_sync(0xFFFFFFFFu, l0, 2);
        l1 += __shfl_xor_sync(0xFFFFFFFFu, l1, 1);
        l1 += __shfl_xor_sync(0xFFFFFFFFu, l1, 2);
        l0 += __expf(snk - m0);
        l1 += __expf(snk - m1);
        const float inv0 = 1.f / l0, inv1 = 1.f / l1;

        const int r0 = i_base + (lane >> 2);
        #pragma unroll
        for (int dn = 0; dn < 8; dn++) {
            const int col = h * 64 + dn * 8 + 2 * (lane & 3);
            const __half2 o0 = __floats2half2_rn(ofr[dn][0] * inv0, ofr[dn][1] * inv0);
            const __half2 o1 = __floats2half2_rn(ofr[dn][2] * inv1, ofr[dn][3] * inv1);
            *reinterpret_cast<__half2*>(out_hi + (size_t)r0 * Q_SIZE + col)       = o0;
            *reinterpret_cast<__half2*>(out_hi + (size_t)(r0 + 8) * Q_SIZE + col) = o1;
        }
    }
}

// ---------------------------------------------------------------------------
// Launch — serial chain, default stream.
// ---------------------------------------------------------------------------
extern "C" void kernel_launch(void* const* d_in, const int* in_sizes, int n_in,
                              void* d_out, int out_size)
{
    const int*   positions = (const int*)  d_in[0];
    const float* hidden    = (const float*)d_in[1];
    const float* W_qkv     = (const float*)d_in[2];
    const float* b_qkv     = (const float*)d_in[3];
    const float* W_o       = (const float*)d_in[4];
    const float* b_o       = (const float*)d_in[5];
    const float* sinks     = (const float*)d_in[6];
    float* out = (float*)d_out;

    float *qkv, *rc, *rs;
    __half *h_hi, *wq_hi, *wo_hi, *a_hi, *v16;
    cudaGetSymbolAddress((void**)&qkv,   g_qkv);
    cudaGetSymbolAddress((void**)&h_hi,  g_h_hi);
    cudaGetSymbolAddress((void**)&wq_hi, g_wq_hi);
    cudaGetSymbolAddress((void**)&wo_hi, g_wo_hi);
    cudaGetSymbolAddress((void**)&a_hi,  g_a_hi);
    cudaGetSymbolAddress((void**)&rc,    g_rcos);
    cudaGetSymbolAddress((void**)&rs,    g_rsin);
    cudaGetSymbolAddress((void**)&v16,   g_v16);

    static bool attr_done = false;
    if (!attr_done) {
        cudaFuncSetAttribute(qkv_fused_kernel,
                             cudaFuncAttributeMaxDynamicSharedMemorySize, GEMM_DSMEM);
        cudaFuncSetAttribute(ogemm_kernel,
                             cudaFuncAttributeMaxDynamicSharedMemorySize, GEMM_DSMEM);
        cudaFuncSetAttribute(attn_mma_kernel,
                             cudaFuncAttributeMaxDynamicSharedMemorySize, ATTN_DSMEM);
        attr_done = true;
    }

    // 0) preprocessing: hidden->fp16, W_qkv transpose, rope table
    preproc_kernel<<<PP_TOTAL_BLOCKS, 256>>>(hidden, W_qkv, positions,
                                             h_hi, wq_hi, rc, rs);
    // 1) QKV projection + W_o transpose riding the wave-2 tail
    qkv_fused_kernel<<<QKV_FUSED_GRID, 256, GEMM_DSMEM>>>(
        h_hi, wq_hi, b_qkv, qkv, v16, W_o, wo_hi);
    // 2) tensor-core flash attention (128-query CTAs)
    {
        dim3 grid(T_LEN / 128, N_KV);
        attn_mma_kernel<<<grid, 256, ATTN_DSMEM>>>(qkv, v16, sinks, rc, rs, a_hi);
    }
    // 3) O projection
    {
        dim3 grid(O_NPAD / 128, T_LEN / 128);
        ogemm_kernel<<<grid, 256, GEMM_DSMEM>>>(a_hi, wo_hi, b_o, out,
                                                HIDDEN, Q_SIZE);
    }
}

// round 14
// speedup vs baseline: 1.0007x; 1.0007x over previous
#include <cuda_runtime.h>
#include <cuda_fp16.h>
#include <cstdint>
#include <cmath>

// ---------------------------------------------------------------------------
// GPT-OSS attention block on sm_100 (legacy mma.sync path).
// Round 14: R12 structure (fused preproc incl. both weight transposes) +
// R13's 128-query attention CTAs. Tail-fill experiment reverted (per-launch
// smem sizing made it occupancy-poisoned).
// ---------------------------------------------------------------------------

#define T_LEN      1536
#define HIDDEN     2880
#define N_HEADS    64
#define N_KV       8
#define HEAD_DIM   64
#define WINDOW     128
#define Q_SIZE     4096
#define KV_SIZE    512
#define QKV_COLS   5120
#define O_NPAD     2944
#define ATT_SCALE  0.125f

// ---------------- scratch ---------------------------------------------------
__device__ __align__(256) float  g_qkv  [(size_t)T_LEN * QKV_COLS];
__device__ __align__(256) __half g_v16  [(size_t)T_LEN * KV_SIZE];
__device__ __align__(256) __half g_h_hi [(size_t)T_LEN * HIDDEN];
__device__ __align__(256) __half g_wq_hi[(size_t)QKV_COLS * HIDDEN];
__device__ __align__(256) __half g_wo_hi[(size_t)O_NPAD * Q_SIZE];
__device__ __align__(256) __half g_a_hi [(size_t)T_LEN * Q_SIZE];
__device__ __align__(256) float  g_rcos [(size_t)T_LEN * 32];
__device__ __align__(256) float  g_rsin [(size_t)T_LEN * 32];

// ---------------- helpers ---------------------------------------------------
static __device__ __forceinline__ uint32_t smem_u32(const void* p) {
    uint32_t a;
    asm("{ .reg .u64 t; cvta.to.shared.u64 t, %1; cvt.u32.u64 %0, t; }"
        : "=r"(a) : "l"(p));
    return a;
}

#define CP_ASYNC16(dst, src) \
    asm volatile("cp.async.cg.shared.global [%0], [%1], 16;" :: "r"(dst), "l"(src))
#define CP_COMMIT() asm volatile("cp.async.commit_group;")
#define CP_WAIT1()  asm volatile("cp.async.wait_group 1;")
#define CP_WAIT0()  asm volatile("cp.async.wait_group 0;")

static __device__ __forceinline__ void ldsm4(uint32_t* r, uint32_t addr) {
    asm volatile("ldmatrix.sync.aligned.m8n8.x4.shared.b16 {%0,%1,%2,%3}, [%4];"
                 : "=r"(r[0]), "=r"(r[1]), "=r"(r[2]), "=r"(r[3]) : "r"(addr));
}

static __device__ __forceinline__ void ldsm4t(uint32_t* r, uint32_t addr) {
    asm volatile("ldmatrix.sync.aligned.m8n8.x4.trans.shared.b16 {%0,%1,%2,%3}, [%4];"
                 : "=r"(r[0]), "=r"(r[1]), "=r"(r[2]), "=r"(r[3]) : "r"(addr));
}

static __device__ __forceinline__ void mma16816(float* d, const uint32_t* a,
                                                uint32_t b0, uint32_t b1) {
    asm volatile("mma.sync.aligned.m16n8k16.row.col.f32.f16.f16.f32 "
                 "{%0,%1,%2,%3}, {%4,%5,%6,%7}, {%8,%9}, {%0,%1,%2,%3};"
                 : "+f"(d[0]), "+f"(d[1]), "+f"(d[2]), "+f"(d[3])
                 : "r"(a[0]), "r"(a[1]), "r"(a[2]), "r"(a[3]), "r"(b0), "r"(b1));
}

// ---------------------------------------------------------------------------
// 1-pass fp16 HMMA GEMM (identical to R12). V tiles store fp16 to v16.
// ---------------------------------------------------------------------------
#define GS           3
#define TILE_BYTES   16384
#define STAGE_BYTES  (2 * TILE_BYTES)
#define GEMM_DSMEM   (GS * STAGE_BYTES + 1024)
#define V_COL0       4608

static __device__ __forceinline__ void load_chunk(
    uint32_t st,
    const __half* __restrict__ Ah, const __half* __restrict__ Bh,
    int m0, int n0, int kk, int K, int tid)
{
    #pragma unroll
    for (int i = 0; i < 4; i++) {
        int ch  = tid + (i << 8);
        int rw  = ch >> 3;
        int c16 = ch & 7;
        uint32_t off = (uint32_t)(rw << 7) + (uint32_t)(c16 << 4);
        uint32_t sw  = off ^ ((off >> 3) & 0x70);
        const char* sa = (const char*)(Ah + (size_t)(m0 + rw) * K + kk) + (c16 << 4);
        const char* sb = (const char*)(Bh + (size_t)(n0 + rw) * K + kk) + (c16 << 4);
        CP_ASYNC16(st + sw,              sa);
        CP_ASYNC16(st + TILE_BYTES + sw, sb);
    }
}

__global__ __launch_bounds__(256, 2)
void hgemm1_kernel(const __half* __restrict__ A_hi,
                   const __half* __restrict__ B_hi,
                   const float* __restrict__ bias, float* __restrict__ C,
                   __half* __restrict__ v16,
                   int Nreal, int K)
{
    extern __shared__ char dynsmem[];
    const uint32_t tile0 = (smem_u32(dynsmem) + 1023u) & ~1023u;

    const int tid  = threadIdx.x;
    const int wid  = tid >> 5;
    const int lane = tid & 31;
    const int m0   = blockIdx.y * 128;
    const int n0   = blockIdx.x * 128;
    const int wm   = (wid & 1) * 64;
    const int wn   = (wid >> 1) * 32;

    const int r7 = lane & 7;
    const int q  = lane >> 3;
    const int rA = ((q & 1) << 3) + r7;
    const int cq = q >> 1;

    const int nch = K >> 6;

    float acc[4][4][4];
    #pragma unroll
    for (int a = 0; a < 4; a++)
        #pragma unroll
        for (int b = 0; b < 4; b++)
            #pragma unroll
            for (int c = 0; c < 4; c++) acc[a][b][c] = 0.0f;

    #pragma unroll
    for (int c = 0; c < GS - 1; c++) {
        load_chunk(tile0 + c * STAGE_BYTES, A_hi, B_hi, m0, n0, c << 6, K, tid);
        CP_COMMIT();
    }

    int stage_c = 0, stage_p = GS - 1;
    for (int c = 0; c < nch; c++) {
        CP_WAIT1();
        __syncthreads();

        if (c + GS - 1 < nch)
            load_chunk(tile0 + stage_p * STAGE_BYTES, A_hi, B_hi,
                       m0, n0, (c + GS - 1) << 6, K, tid);
        CP_COMMIT();
        if (++stage_p == GS) stage_p = 0;

        const uint32_t aB = tile0 + stage_c * STAGE_BYTES;
        const uint32_t bB = aB + TILE_BYTES;
        if (++stage_c == GS) stage_c = 0;

        #pragma unroll
        for (int ks = 0; ks < 4; ks++) {
            uint32_t afr[4][4], bfr[2][4];
            const uint32_t chsw = (uint32_t)(((ks * 2 + cq) ^ r7) << 4);
            #pragma unroll
            for (int mt = 0; mt < 4; mt++)
                ldsm4(afr[mt], aB + (uint32_t)((wm + mt * 16 + rA) << 7) + chsw);
            #pragma unroll
            for (int ng = 0; ng < 2; ng++)
                ldsm4(bfr[ng], bB + (uint32_t)((wn + ng * 16 + rA) << 7) + chsw);

            #pragma unroll
            for (int mt = 0; mt < 4; mt++)
                #pragma unroll
                for (int nt = 0; nt < 4; nt++) {
                    const int ng = nt >> 1, hl = nt & 1;
                    mma16816(acc[mt][nt], afr[mt], bfr[ng][hl], bfr[ng][hl + 2]);
                }
        }
    }

    const int trow = lane >> 2;
    const int tcol = (lane & 3) * 2;
    const bool vtile = (v16 != nullptr) && (n0 >= V_COL0);
    #pragma unroll
    for (int mt = 0; mt < 4; mt++) {
        #pragma unroll
        for (int nt = 0; nt < 4; nt++) {
            const int col = n0 + wn + nt * 8 + tcol;
            if (col < Nreal) {
                const float2 b2 = *reinterpret_cast<const float2*>(bias + col);
                const int row0 = m0 + wm + mt * 16 + trow;
                float2 o0, o1;
                o0.x = acc[mt][nt][0] + b2.x;  o0.y = acc[mt][nt][1] + b2.y;
                o1.x = acc[mt][nt][2] + b2.x;  o1.y = acc[mt][nt][3] + b2.y;
                if (vtile) {
                    const int vc = col - V_COL0;
                    *reinterpret_cast<__half2*>(v16 + (size_t)row0 * KV_SIZE + vc) =
                        __floats2half2_rn(o0.x, o0.y);
                    *reinterpret_cast<__half2*>(v16 + (size_t)(row0 + 8) * KV_SIZE + vc) =
                        __floats2half2_rn(o1.x, o1.y);
                } else {
                    *reinterpret_cast<float2*>(C + (size_t)row0 * Nreal + col)       = o0;
                    *reinterpret_cast<float2*>(C + (size_t)(row0 + 8) * Nreal + col) = o1;
                }
            }
        }
    }
}

// ---------------------------------------------------------------------------
// Fused preprocessing (R12): hidden->fp16, both weight transposes, rope table.
// ---------------------------------------------------------------------------
#define PP_SPLIT_BLOCKS  4320
#define PP_THI1_BLOCKS   7200    // (5120/32) x (2880/64)
#define PP_THI2_BLOCKS   5888    // (2944/32) x (4096/64)
#define PP_ROPE_BLOCKS   192
#define PP_TOTAL_BLOCKS  (PP_SPLIT_BLOCKS + PP_THI1_BLOCKS + PP_THI2_BLOCKS + PP_ROPE_BLOCKS)

__global__ __launch_bounds__(256)
void preproc_kernel(const float* __restrict__ hidden,
                    const float* __restrict__ W_qkv,
                    const float* __restrict__ W_o,
                    const int* __restrict__ positions,
                    __half* __restrict__ h_hi,
                    __half* __restrict__ wq_hi,
                    __half* __restrict__ wo_hi,
                    float* __restrict__ rcos,
                    float* __restrict__ rsin)
{
    __shared__ float tile[64][33];
    const int bid = blockIdx.x;
    const int tid = threadIdx.x;

    if (bid < PP_SPLIT_BLOCKS) {
        const int i = bid * 256 + tid;
        float4 v = reinterpret_cast<const float4*>(hidden)[i];
        reinterpret_cast<__half2*>(h_hi)[2 * i + 0] =
            __halves2half2(__float2half_rn(v.x), __float2half_rn(v.y));
        reinterpret_cast<__half2*>(h_hi)[2 * i + 1] =
            __halves2half2(__float2half_rn(v.z), __float2half_rn(v.w));
        return;
    }

    if (bid < PP_SPLIT_BLOCKS + PP_THI1_BLOCKS + PP_THI2_BLOCKS) {
        const bool j1 = bid < PP_SPLIT_BLOCKS + PP_THI1_BLOCKS;
        const int  b  = j1 ? (bid - PP_SPLIT_BLOCKS)
                           : (bid - PP_SPLIT_BLOCKS - PP_THI1_BLOCKS);
        const int  nx = j1 ? (QKV_COLS / 32) : (O_NPAD / 32);
        const int  K  = j1 ? HIDDEN : Q_SIZE;
        const int  N  = j1 ? QKV_COLS : HIDDEN;
        const float* __restrict__ W = j1 ? W_qkv : W_o;
        __half* __restrict__ dst    = j1 ? wq_hi : wo_hi;

        const int n0 = (b % nx) * 32;
        const int k0 = (b / nx) * 64;

        #pragma unroll
        for (int i = 0; i < 2; i++) {
            const int id = tid + (i << 8);
            const int kr = id >> 3;
            const int c4 = (id & 7) * 4;
            const int n  = n0 + c4;
            float4 v = make_float4(0.f, 0.f, 0.f, 0.f);
            if (n < N)
                v = *reinterpret_cast<const float4*>(W + (size_t)(k0 + kr) * N + n);
            tile[kr][c4 + 0] = v.x;  tile[kr][c4 + 1] = v.y;
            tile[kr][c4 + 2] = v.z;  tile[kr][c4 + 3] = v.w;
        }
        __syncthreads();

        const int nr = tid >> 3;
        const int kc = (tid & 7) * 8;
        __half hb[8];
        #pragma unroll
        for (int x = 0; x < 8; x++)
            hb[x] = __float2half_rn(tile[kc + x][nr]);
        *reinterpret_cast<uint4*>(dst + (size_t)(n0 + nr) * K + k0 + kc) =
            *reinterpret_cast<const uint4*>(hb);
        return;
    }

    // rope table
    {
        const int i = (bid - PP_SPLIT_BLOCKS - PP_THI1_BLOCKS - PP_THI2_BLOCKS) * 256 + tid;
        if (i >= T_LEN * 32) return;
        const int d = i & 31;
        const int t = i >> 5;

        const float p = (float)positions[t];
        const float lnB   = logf(150000.0f);
        const float freq  = expf(lnB * ((float)d / 32.0f));
        const float conc  = 0.1f * logf(32.0f) + 1.0f;
        const float twoPi = 6.283185307179586f;
        const float low   = 32.0f * logf(4096.0f / (32.0f * twoPi)) / lnB;
        const float high  = 32.0f * logf(4096.0f / (1.0f  * twoPi)) / lnB;
        float ramp = ((float)d - low) / (high - low);
        ramp = fminf(fmaxf(ramp, 0.0f), 1.0f);
        const float inv_freq = ramp / (32.0f * freq) + (1.0f - ramp) / freq;

        const float ang = p * inv_freq;
        rcos[i] = cosf(ang) * conc;
        rsin[i] = sinf(ang) * conc;
    }
}

// ---------------------------------------------------------------------------
// Tensor-core flash attention, 128-query CTAs (from R13; bit-exact).
// ---------------------------------------------------------------------------
#define AROWS       256
#define ATTN_DSMEM  (32768 + 32768 + 16384)   // 81920

__global__ __launch_bounds__(256, 2)
void attn_mma_kernel(const float* __restrict__ qkv,
                     const __half* __restrict__ v16,
                     const float* __restrict__ sinks,
                     const float* __restrict__ rcos,
                     const float* __restrict__ rsin,
                     __half* __restrict__ out_hi)
{
    extern __shared__ char asmem[];
    const uint32_t sbase = smem_u32(asmem);
    const uint32_t Ks = sbase;
    const uint32_t Vs = sbase + 32768;

    const int tid  = threadIdx.x;
    const int warp = tid >> 5;
    const int lane = tid & 31;
    const int i0   = blockIdx.x * 128;
    const int kv   = blockIdx.y;
    const int h    = kv * 8 + warp;
    const uint32_t Qs = sbase + 65536 + warp * 2048;

    for (int idx = tid; idx < AROWS * 8; idx += 256) {
        const int r = idx >> 3, c16 = idx & 7;
        const int j = i0 - 128 + r;
        const uint32_t off = (uint32_t)(r * 128) + ((uint32_t)(c16 ^ (r & 7)) << 4);
        if (j >= 0) {
            CP_ASYNC16(Vs + off,
                       (const char*)(v16 + (size_t)j * KV_SIZE + kv * 64) + (c16 << 4));
        } else {
            *reinterpret_cast<uint4*>(asmem + 32768 + off) = make_uint4(0u, 0u, 0u, 0u);
        }
    }
    CP_COMMIT();

    for (int idx = tid; idx < AROWS * 16; idx += 256) {
        const int r = idx >> 4, d2 = idx & 15;
        const int j = i0 - 128 + r;
        float2 y1 = make_float2(0.f, 0.f), y2 = make_float2(0.f, 0.f);
        if (j >= 0) {
            const float* src = qkv + (size_t)j * QKV_COLS + Q_SIZE + kv * 64;
            const float2 x1 = *reinterpret_cast<const float2*>(src + 2 * d2);
            const float2 x2 = *reinterpret_cast<const float2*>(src + 2 * d2 + 32);
            const float2 cc = *reinterpret_cast<const float2*>(rcos + j * 32 + 2 * d2);
            const float2 ss = *reinterpret_cast<const float2*>(rsin + j * 32 + 2 * d2);
            y1.x = x1.x * cc.x - x2.x * ss.x;  y1.y = x1.y * cc.y - x2.y * ss.y;
            y2.x = x2.x * cc.x + x1.x * ss.x;  y2.y = x2.y * cc.y + x1.y * ss.y;
        }
        const int d2b = d2 + 16;
        const uint32_t sw1 = (uint32_t)(r * 128) +
                             ((uint32_t)((d2 >> 2) ^ (r & 7)) << 4) + (d2 & 3) * 4;
        const uint32_t sw2 = (uint32_t)(r * 128) +
                             ((uint32_t)((d2b >> 2) ^ (r & 7)) << 4) + (d2b & 3) * 4;
        *reinterpret_cast<__half2*>(asmem + sw1) = __floats2half2_rn(y1.x, y1.y);
        *reinterpret_cast<__half2*>(asmem + sw2) = __floats2half2_rn(y2.x, y2.y);
    }
    CP_WAIT0();
    __syncthreads();

    const float snk = sinks[h];
    const int r7 = lane & 7;
    const int qq = lane >> 3;
    const int rA = ((qq & 1) << 3) + r7;
    const int cq = qq >> 1;
    const int vrow_l = (lane & 7) + ((lane >> 4) << 3);
    const int vnsel  = (lane >> 3) & 1;

    for (int mt = 0; mt < 8; mt++) {
        const int i_base = i0 + mt * 16;

        __syncwarp();
        for (int e = lane; e < 256; e += 32) {
            const int r = e >> 4, d2 = e & 15;
            const int t = i_base + r;
            const float* src = qkv + (size_t)t * QKV_COLS + h * 64;
            const float2 x1 = *reinterpret_cast<const float2*>(src + 2 * d2);
            const float2 x2 = *reinterpret_cast<const float2*>(src + 2 * d2 + 32);
            const float2 cc = *reinterpret_cast<const float2*>(rcos + t * 32 + 2 * d2);
            const float2 ss = *reinterpret_cast<const float2*>(rsin + t * 32 + 2 * d2);
            float2 y1, y2;
            y1.x = x1.x * cc.x - x2.x * ss.x;  y1.y = x1.y * cc.y - x2.y * ss.y;
            y2.x = x2.x * cc.x + x1.x * ss.x;  y2.y = x2.y * cc.y + x1.y * ss.y;
            const int d2b = d2 + 16;
            const uint32_t sw1 = (uint32_t)(r * 128) +
                                 ((uint32_t)((d2 >> 2) ^ (r & 7)) << 4) + (d2 & 3) * 4;
            const uint32_t sw2 = (uint32_t)(r * 128) +
                                 ((uint32_t)((d2b >> 2) ^ (r & 7)) << 4) + (d2b & 3) * 4;
            *reinterpret_cast<__half2*>(asmem + 65536 + warp * 2048 + sw1) =
                __floats2half2_rn(y1.x, y1.y);
            *reinterpret_cast<__half2*>(asmem + 65536 + warp * 2048 + sw2) =
                __floats2half2_rn(y2.x, y2.y);
        }
        __syncwarp();

        uint32_t aQ[4][4];
        #pragma unroll
        for (int ks = 0; ks < 4; ks++)
            ldsm4(aQ[ks], Qs + (uint32_t)(rA * 128) +
                          ((uint32_t)(((2 * ks + cq) ^ r7)) << 4));

        float m0 = snk, m1 = snk, l0 = 0.f, l1 = 0.f;
        float ofr[8][4];
        #pragma unroll
        for (int dn = 0; dn < 8; dn++)
            #pragma unroll
            for (int c = 0; c < 4; c++) ofr[dn][c] = 0.f;

        const int b_lo = mt >> 1;
        for (int bb = 0; bb < 5; bb++) {
            const int b = b_lo + bb;

            float sf[4][4];
            #pragma unroll
            for (int nt = 0; nt < 4; nt++)
                #pragma unroll
                for (int c = 0; c < 4; c++) sf[nt][c] = 0.f;

            #pragma unroll
            for (int ks = 0; ks < 4; ks++) {
                uint32_t bk0[4], bk1[4];
                const uint32_t chsw = (uint32_t)(((2 * ks + cq) ^ r7)) << 4;
                ldsm4(bk0, Ks + (uint32_t)((32 * b + rA) * 128) + chsw);
                ldsm4(bk1, Ks + (uint32_t)((32 * b + 16 + rA) * 128) + chsw);
                mma16816(sf[0], aQ[ks], bk0[0], bk0[2]);
                mma16816(sf[1], aQ[ks], bk0[1], bk0[3]);
                mma16816(sf[2], aQ[ks], bk1[0], bk1[2]);
                mma16816(sf[3], aQ[ks], bk1[1], bk1[3]);
            }

            const int jb  = i0 - 128 + 32 * b;
            const int ir0 = i_base + (lane >> 2);
            const int ir1 = ir0 + 8;
            float bm0 = -1e30f, bm1 = -1e30f;
            #pragma unroll
            for (int nt = 0; nt < 4; nt++) {
                const int jc = jb + nt * 8 + 2 * (lane & 3);
                #pragma unroll
                for (int c = 0; c < 2; c++) {
                    const int j = jc + c;
                    const float s0 = sf[nt][c] * ATT_SCALE;
                    const float s1 = sf[nt][c + 2] * ATT_SCALE;
                    const bool ok0 = (j >= 0) && (j <= ir0) && (ir0 - j < 128);
                    const bool ok1 = (j >= 0) && (j <= ir1) && (ir1 - j < 128);
                    sf[nt][c]     = ok0 ? s0 : -1e30f;
                    sf[nt][c + 2] = ok1 ? s1 : -1e30f;
                    bm0 = fmaxf(bm0, sf[nt][c]);
                    bm1 = fmaxf(bm1, sf[nt][c + 2]);
                }
            }
            bm0 = fmaxf(bm0, __shfl_xor_sync(0xFFFFFFFFu, bm0, 1));
            bm0 = fmaxf(bm0, __shfl_xor_sync(0xFFFFFFFFu, bm0, 2));
            bm1 = fmaxf(bm1, __shfl_xor_sync(0xFFFFFFFFu, bm1, 1));
            bm1 = fmaxf(bm1, __shfl_xor_sync(0xFFFFFFFFu, bm1, 2));

            const float nm0 = fmaxf(m0, bm0), nm1 = fmaxf(m1, bm1);
            const float sc0 = __expf(m0 - nm0), sc1 = __expf(m1 - nm1);
            m0 = nm0; m1 = nm1;
            l0 *= sc0; l1 *= sc1;
            #pragma unroll
            for (int dn = 0; dn < 8; dn++) {
                ofr[dn][0] *= sc0; ofr[dn][1] *= sc0;
                ofr[dn][2] *= sc1; ofr[dn][3] *= sc1;
            }

            uint32_t P01[4], P23[4];
            #pragma unroll
            for (int nt = 0; nt < 4; nt++) {
                const float p0 = __expf(sf[nt][0] - m0);
                const float p1 = __expf(sf[nt][1] - m0);
                const float p2 = __expf(sf[nt][2] - m1);
                const float p3 = __expf(sf[nt][3] - m1);
                l0 += p0 + p1;  l1 += p2 + p3;
                const __half2 h01 = __floats2half2_rn(p0, p1);
                const __half2 h23 = __floats2half2_rn(p2, p3);
                P01[nt] = *reinterpret_cast<const uint32_t*>(&h01);
                P23[nt] = *reinterpret_cast<const uint32_t*>(&h23);
            }

            #pragma unroll
            for (int kt = 0; kt < 2; kt++) {
                uint32_t aP[4] = {P01[2 * kt], P23[2 * kt],
                                  P01[2 * kt + 1], P23[2 * kt + 1]};
                const int vr = 32 * b + 16 * kt + vrow_l;
                #pragma unroll
                for (int dp = 0; dp < 4; dp++) {
                    uint32_t bv[4];
                    ldsm4t(bv, Vs + (uint32_t)(vr * 128) +
                               ((uint32_t)(((2 * dp + vnsel) ^ (vr & 7))) << 4));
                    mma16816(ofr[2 * dp],     aP, bv[0], bv[2]);
                    mma16816(ofr[2 * dp + 1], aP, bv[1], bv[3]);
                }
            }
        }

        l0 += __shfl_xor_sync(0xFFFFFFFFu, l0, 1);
        l0 += __shfl_xor_sync(0xFFFFFFFFu, l0, 2);
        l1 += __shfl_xor_sync(0xFFFFFFFFu, l1, 1);
        l1 += __shfl_xor_sync(0xFFFFFFFFu, l1, 2);
        l0 += __expf(snk - m0);
        l1 += __expf(snk - m1);
        const float inv0 = 1.f / l0, inv1 = 1.f / l1;

        const int r0 = i_base + (lane >> 2);
        #pragma unroll
        for (int dn = 0; dn < 8; dn++) {
            const int col = h * 64 + dn * 8 + 2 * (lane & 3);
            const __half2 o0 = __floats2half2_rn(ofr[dn][0] * inv0, ofr[dn][1] * inv0);
            const __half2 o1 = __floats2half2_rn(ofr[dn][2] * inv1, ofr[dn][3] * inv1);
            *reinterpret_cast<__half2*>(out_hi + (size_t)r0 * Q_SIZE + col)       = o0;
            *reinterpret_cast<__half2*>(out_hi + (size_t)(r0 + 8) * Q_SIZE + col) = o1;
        }
    }
}

// ---------------------------------------------------------------------------
// Launch — serial chain, default stream.
// ---------------------------------------------------------------------------
extern "C" void kernel_launch(void* const* d_in, const int* in_sizes, int n_in,
                              void* d_out, int out_size)
{
    const int*   positions = (const int*)  d_in[0];
    const float* hidden    = (const float*)d_in[1];
    const float* W_qkv     = (const float*)d_in[2];
    const float* b_qkv     = (const float*)d_in[3];
    const float* W_o       = (const float*)d_in[4];
    const float* b_o       = (const float*)d_in[5];
    const float* sinks     = (const float*)d_in[6];
    float* out = (float*)d_out;

    float *qkv, *rc, *rs;
    __half *h_hi, *wq_hi, *wo_hi, *a_hi, *v16;
    cudaGetSymbolAddress((void**)&qkv,   g_qkv);
    cudaGetSymbolAddress((void**)&h_hi,  g_h_hi);
    cudaGetSymbolAddress((void**)&wq_hi, g_wq_hi);
    cudaGetSymbolAddress((void**)&wo_hi, g_wo_hi);
    cudaGetSymbolAddress((void**)&a_hi,  g_a_hi);
    cudaGetSymbolAddress((void**)&rc,    g_rcos);
    cudaGetSymbolAddress((void**)&rs,    g_rsin);
    cudaGetSymbolAddress((void**)&v16,   g_v16);

    static bool attr_done = false;
    if (!attr_done) {
        cudaFuncSetAttribute(hgemm1_kernel,
                             cudaFuncAttributeMaxDynamicSharedMemorySize, GEMM_DSMEM);
        cudaFuncSetAttribute(attn_mma_kernel,
                             cudaFuncAttributeMaxDynamicSharedMemorySize, ATTN_DSMEM);
        attr_done = true;
    }

    // 0) fused preprocessing
    preproc_kernel<<<PP_TOTAL_BLOCKS, 256>>>(hidden, W_qkv, W_o, positions,
                                             h_hi, wq_hi, wo_hi, rc, rs);
    // 1) QKV projection (V columns emitted as fp16)
    {
        dim3 grid(QKV_COLS / 128, T_LEN / 128);
        hgemm1_kernel<<<grid, 256, GEMM_DSMEM>>>(h_hi, wq_hi, b_qkv, qkv, v16,
                                                 QKV_COLS, HIDDEN);
    }
    // 2) tensor-core flash attention (128-query CTAs)
    {
        dim3 grid(T_LEN / 128, N_KV);
        attn_mma_kernel<<<grid, 256, ATTN_DSMEM>>>(qkv, v16, sinks, rc, rs, a_hi);
    }
    // 3) O projection
    {
        dim3 grid(O_NPAD / 128, T_LEN / 128);
        hgemm1_kernel<<<grid, 256, GEMM_DSMEM>>>(a_hi, wo_hi, b_o, out, nullptr,
                                                 HIDDEN, Q_SIZE);
    }
}

// round 15
// speedup vs baseline: 1.0199x; 1.0192x over previous
#include <cuda_runtime.h>
#include <cuda_fp16.h>
#include <cstdint>
#include <cmath>

// ---------------------------------------------------------------------------
// GPT-OSS attention block on sm_100 (legacy mma.sync path).
// Round 15: exact R12 base (best: 350.2us) + W_o transpose folded into the
// attention launch as 104 persistent mega-blocks occupying the 104 free
// co-residency slots (192 attn CTAs + 104 wo blocks = 296 = one full wave).
// All arithmetic bit-identical to R12.
// ---------------------------------------------------------------------------

#define T_LEN      1536
#define HIDDEN     2880
#define N_HEADS    64
#define N_KV       8
#define HEAD_DIM   64
#define WINDOW     128
#define Q_SIZE     4096
#define KV_SIZE    512
#define QKV_COLS   5120
#define O_NPAD     2944
#define ATT_SCALE  0.125f

// ---------------- scratch ---------------------------------------------------
__device__ __align__(256) float  g_qkv  [(size_t)T_LEN * QKV_COLS];
__device__ __align__(256) __half g_v16  [(size_t)T_LEN * KV_SIZE];
__device__ __align__(256) __half g_h_hi [(size_t)T_LEN * HIDDEN];
__device__ __align__(256) __half g_wq_hi[(size_t)QKV_COLS * HIDDEN];
__device__ __align__(256) __half g_wo_hi[(size_t)O_NPAD * Q_SIZE];
__device__ __align__(256) __half g_a_hi [(size_t)T_LEN * Q_SIZE];
__device__ __align__(256) float  g_rcos [(size_t)T_LEN * 32];
__device__ __align__(256) float  g_rsin [(size_t)T_LEN * 32];

// ---------------- helpers ---------------------------------------------------
static __device__ __forceinline__ uint32_t smem_u32(const void* p) {
    uint32_t a;
    asm("{ .reg .u64 t; cvta.to.shared.u64 t, %1; cvt.u32.u64 %0, t; }"
        : "=r"(a) : "l"(p));
    return a;
}

#define CP_ASYNC16(dst, src) \
    asm volatile("cp.async.cg.shared.global [%0], [%1], 16;" :: "r"(dst), "l"(src))
#define CP_COMMIT() asm volatile("cp.async.commit_group;")
#define CP_WAIT1()  asm volatile("cp.async.wait_group 1;")
#define CP_WAIT0()  asm volatile("cp.async.wait_group 0;")

static __device__ __forceinline__ void ldsm4(uint32_t* r, uint32_t addr) {
    asm volatile("ldmatrix.sync.aligned.m8n8.x4.shared.b16 {%0,%1,%2,%3}, [%4];"
                 : "=r"(r[0]), "=r"(r[1]), "=r"(r[2]), "=r"(r[3]) : "r"(addr));
}

static __device__ __forceinline__ void ldsm4t(uint32_t* r, uint32_t addr) {
    asm volatile("ldmatrix.sync.aligned.m8n8.x4.trans.shared.b16 {%0,%1,%2,%3}, [%4];"
                 : "=r"(r[0]), "=r"(r[1]), "=r"(r[2]), "=r"(r[3]) : "r"(addr));
}

static __device__ __forceinline__ void mma16816(float* d, const uint32_t* a,
                                                uint32_t b0, uint32_t b1) {
    asm volatile("mma.sync.aligned.m16n8k16.row.col.f32.f16.f16.f32 "
                 "{%0,%1,%2,%3}, {%4,%5,%6,%7}, {%8,%9}, {%0,%1,%2,%3};"
                 : "+f"(d[0]), "+f"(d[1]), "+f"(d[2]), "+f"(d[3])
                 : "r"(a[0]), "r"(a[1]), "r"(a[2]), "r"(a[3]), "r"(b0), "r"(b1));
}

// ---------------------------------------------------------------------------
// 1-pass fp16 HMMA GEMM (identical to R12). V tiles store fp16 to v16.
// ---------------------------------------------------------------------------
#define GS           3
#define TILE_BYTES   16384
#define STAGE_BYTES  (2 * TILE_BYTES)
#define GEMM_DSMEM   (GS * STAGE_BYTES + 1024)
#define V_COL0       4608

static __device__ __forceinline__ void load_chunk(
    uint32_t st,
    const __half* __restrict__ Ah, const __half* __restrict__ Bh,
    int m0, int n0, int kk, int K, int tid)
{
    #pragma unroll
    for (int i = 0; i < 4; i++) {
        int ch  = tid + (i << 8);
        int rw  = ch >> 3;
        int c16 = ch & 7;
        uint32_t off = (uint32_t)(rw << 7) + (uint32_t)(c16 << 4);
        uint32_t sw  = off ^ ((off >> 3) & 0x70);
        const char* sa = (const char*)(Ah + (size_t)(m0 + rw) * K + kk) + (c16 << 4);
        const char* sb = (const char*)(Bh + (size_t)(n0 + rw) * K + kk) + (c16 << 4);
        CP_ASYNC16(st + sw,              sa);
        CP_ASYNC16(st + TILE_BYTES + sw, sb);
    }
}

__global__ __launch_bounds__(256, 2)
void hgemm1_kernel(const __half* __restrict__ A_hi,
                   const __half* __restrict__ B_hi,
                   const float* __restrict__ bias, float* __restrict__ C,
                   __half* __restrict__ v16,
                   int Nreal, int K)
{
    extern __shared__ char dynsmem[];
    const uint32_t tile0 = (smem_u32(dynsmem) + 1023u) & ~1023u;

    const int tid  = threadIdx.x;
    const int wid  = tid >> 5;
    const int lane = tid & 31;
    const int m0   = blockIdx.y * 128;
    const int n0   = blockIdx.x * 128;
    const int wm   = (wid & 1) * 64;
    const int wn   = (wid >> 1) * 32;

    const int r7 = lane & 7;
    const int q  = lane >> 3;
    const int rA = ((q & 1) << 3) + r7;
    const int cq = q >> 1;

    const int nch = K >> 6;

    float acc[4][4][4];
    #pragma unroll
    for (int a = 0; a < 4; a++)
        #pragma unroll
        for (int b = 0; b < 4; b++)
            #pragma unroll
            for (int c = 0; c < 4; c++) acc[a][b][c] = 0.0f;

    #pragma unroll
    for (int c = 0; c < GS - 1; c++) {
        load_chunk(tile0 + c * STAGE_BYTES, A_hi, B_hi, m0, n0, c << 6, K, tid);
        CP_COMMIT();
    }

    int stage_c = 0, stage_p = GS - 1;
    for (int c = 0; c < nch; c++) {
        CP_WAIT1();
        __syncthreads();

        if (c + GS - 1 < nch)
            load_chunk(tile0 + stage_p * STAGE_BYTES, A_hi, B_hi,
                       m0, n0, (c + GS - 1) << 6, K, tid);
        CP_COMMIT();
        if (++stage_p == GS) stage_p = 0;

        const uint32_t aB = tile0 + stage_c * STAGE_BYTES;
        const uint32_t bB = aB + TILE_BYTES;
        if (++stage_c == GS) stage_c = 0;

        #pragma unroll
        for (int ks = 0; ks < 4; ks++) {
            uint32_t afr[4][4], bfr[2][4];
            const uint32_t chsw = (uint32_t)(((ks * 2 + cq) ^ r7) << 4);
            #pragma unroll
            for (int mt = 0; mt < 4; mt++)
                ldsm4(afr[mt], aB + (uint32_t)((wm + mt * 16 + rA) << 7) + chsw);
            #pragma unroll
            for (int ng = 0; ng < 2; ng++)
                ldsm4(bfr[ng], bB + (uint32_t)((wn + ng * 16 + rA) << 7) + chsw);

            #pragma unroll
            for (int mt = 0; mt < 4; mt++)
                #pragma unroll
                for (int nt = 0; nt < 4; nt++) {
                    const int ng = nt >> 1, hl = nt & 1;
                    mma16816(acc[mt][nt], afr[mt], bfr[ng][hl], bfr[ng][hl + 2]);
                }
        }
    }

    const int trow = lane >> 2;
    const int tcol = (lane & 3) * 2;
    const bool vtile = (v16 != nullptr) && (n0 >= V_COL0);
    #pragma unroll
    for (int mt = 0; mt < 4; mt++) {
        #pragma unroll
        for (int nt = 0; nt < 4; nt++) {
            const int col = n0 + wn + nt * 8 + tcol;
            if (col < Nreal) {
                const float2 b2 = *reinterpret_cast<const float2*>(bias + col);
                const int row0 = m0 + wm + mt * 16 + trow;
                float2 o0, o1;
                o0.x = acc[mt][nt][0] + b2.x;  o0.y = acc[mt][nt][1] + b2.y;
                o1.x = acc[mt][nt][2] + b2.x;  o1.y = acc[mt][nt][3] + b2.y;
                if (vtile) {
                    const int vc = col - V_COL0;
                    *reinterpret_cast<__half2*>(v16 + (size_t)row0 * KV_SIZE + vc) =
                        __floats2half2_rn(o0.x, o0.y);
                    *reinterpret_cast<__half2*>(v16 + (size_t)(row0 + 8) * KV_SIZE + vc) =
                        __floats2half2_rn(o1.x, o1.y);
                } else {
                    *reinterpret_cast<float2*>(C + (size_t)row0 * Nreal + col)       = o0;
                    *reinterpret_cast<float2*>(C + (size_t)(row0 + 8) * Nreal + col) = o1;
                }
            }
        }
    }
}

// ---------------------------------------------------------------------------
// Preprocessing A: hidden->fp16 (4320), W_qkv transpose (7200), rope (192).
// (W_o transpose moved into the attention launch.)
// ---------------------------------------------------------------------------
#define PP_SPLIT_BLOCKS  4320
#define PP_THI1_BLOCKS   7200
#define PP_ROPE_BLOCKS   192
#define PP_TOTAL_BLOCKS  (PP_SPLIT_BLOCKS + PP_THI1_BLOCKS + PP_ROPE_BLOCKS)

__global__ __launch_bounds__(256)
void preproc_kernel(const float* __restrict__ hidden,
                    const float* __restrict__ W_qkv,
                    const int* __restrict__ positions,
                    __half* __restrict__ h_hi,
                    __half* __restrict__ wq_hi,
                    float* __restrict__ rcos,
                    float* __restrict__ rsin)
{
    __shared__ float tile[64][33];
    const int bid = blockIdx.x;
    const int tid = threadIdx.x;

    if (bid < PP_SPLIT_BLOCKS) {
        const int i = bid * 256 + tid;
        float4 v = reinterpret_cast<const float4*>(hidden)[i];
        reinterpret_cast<__half2*>(h_hi)[2 * i + 0] =
            __halves2half2(__float2half_rn(v.x), __float2half_rn(v.y));
        reinterpret_cast<__half2*>(h_hi)[2 * i + 1] =
            __halves2half2(__float2half_rn(v.z), __float2half_rn(v.w));
        return;
    }

    if (bid < PP_SPLIT_BLOCKS + PP_THI1_BLOCKS) {
        const int b  = bid - PP_SPLIT_BLOCKS;
        const int nx = QKV_COLS / 32;
        const int K  = HIDDEN;
        const int N  = QKV_COLS;

        const int n0 = (b % nx) * 32;
        const int k0 = (b / nx) * 64;

        #pragma unroll
        for (int i = 0; i < 2; i++) {
            const int id = tid + (i << 8);
            const int kr = id >> 3;
            const int c4 = (id & 7) * 4;
            const int n  = n0 + c4;
            float4 v = make_float4(0.f, 0.f, 0.f, 0.f);
            if (n < N)
                v = *reinterpret_cast<const float4*>(W_qkv + (size_t)(k0 + kr) * N + n);
            tile[kr][c4 + 0] = v.x;  tile[kr][c4 + 1] = v.y;
            tile[kr][c4 + 2] = v.z;  tile[kr][c4 + 3] = v.w;
        }
        __syncthreads();

        const int nr = tid >> 3;
        const int kc = (tid & 7) * 8;
        __half hb[8];
        #pragma unroll
        for (int x = 0; x < 8; x++)
            hb[x] = __float2half_rn(tile[kc + x][nr]);
        *reinterpret_cast<uint4*>(wq_hi + (size_t)(n0 + nr) * K + k0 + kc) =
            *reinterpret_cast<const uint4*>(hb);
        return;
    }

    // rope table
    {
        const int i = (bid - PP_SPLIT_BLOCKS - PP_THI1_BLOCKS) * 256 + tid;
        if (i >= T_LEN * 32) return;
        const int d = i & 31;
        const int t = i >> 5;

        const float p = (float)positions[t];
        const float lnB   = logf(150000.0f);
        const float freq  = expf(lnB * ((float)d / 32.0f));
        const float conc  = 0.1f * logf(32.0f) + 1.0f;
        const float twoPi = 6.283185307179586f;
        const float low   = 32.0f * logf(4096.0f / (32.0f * twoPi)) / lnB;
        const float high  = 32.0f * logf(4096.0f / (1.0f  * twoPi)) / lnB;
        float ramp = ((float)d - low) / (high - low);
        ramp = fminf(fmaxf(ramp, 0.0f), 1.0f);
        const float inv_freq = ramp / (32.0f * freq) + (1.0f - ramp) / freq;

        const float ang = p * inv_freq;
        rcos[i] = cosf(ang) * conc;
        rsin[i] = sinf(ang) * conc;
    }
}

// ---------------------------------------------------------------------------
// Attention launch: 192 attn CTAs (R12's 64-query form) + 104 persistent
// W_o-transpose mega-blocks (fill the 104 free co-residency slots).
// ---------------------------------------------------------------------------
#define AROWS        192
#define ATTN_DSMEM   65536
#define ATTN_CTAS    192          // 24 qblocks x 8 kv heads
#define WO_MEGA      104
#define WO_TILES_TOT 5888         // (2944/32) x (4096/64)

__global__ __launch_bounds__(256, 2)
void attn_mma_kernel(const float* __restrict__ qkv,
                     const __half* __restrict__ v16,
                     const float* __restrict__ sinks,
                     const float* __restrict__ rcos,
                     const float* __restrict__ rsin,
                     __half* __restrict__ out_hi,
                     const float* __restrict__ W_o,
                     __half* __restrict__ wo_hi)
{
    extern __shared__ char asmem[];
    const int bid = blockIdx.x;
    const int tid = threadIdx.x;

    // ---------------- W_o transpose mega-blocks -----------------------------
    if (bid >= ATTN_CTAS) {
        float (*tile)[33] = reinterpret_cast<float(*)[33]>(asmem);
        const int nx = O_NPAD / 32;            // 92
        for (int b = bid - ATTN_CTAS; b < WO_TILES_TOT; b += WO_MEGA) {
            const int n0 = (b % nx) * 32;
            const int k0 = (b / nx) * 64;

            #pragma unroll
            for (int i = 0; i < 2; i++) {
                const int id = tid + (i << 8);
                const int kr = id >> 3;
                const int c4 = (id & 7) * 4;
                const int n  = n0 + c4;
                float4 v = make_float4(0.f, 0.f, 0.f, 0.f);
                if (n < HIDDEN)
                    v = *reinterpret_cast<const float4*>(
                        W_o + (size_t)(k0 + kr) * HIDDEN + n);
                tile[kr][c4 + 0] = v.x;  tile[kr][c4 + 1] = v.y;
                tile[kr][c4 + 2] = v.z;  tile[kr][c4 + 3] = v.w;
            }
            __syncthreads();

            const int nr = tid >> 3;
            const int kc = (tid & 7) * 8;
            __half hb[8];
            #pragma unroll
            for (int x = 0; x < 8; x++)
                hb[x] = __float2half_rn(tile[kc + x][nr]);
            *reinterpret_cast<uint4*>(wo_hi + (size_t)(n0 + nr) * Q_SIZE + k0 + kc) =
                *reinterpret_cast<const uint4*>(hb);
            __syncthreads();
        }
        return;
    }

    // ---------------- flash attention (identical to R12) --------------------
    const uint32_t sbase = smem_u32(asmem);
    const uint32_t Ks = sbase;
    const uint32_t Vs = sbase + 24576;

    const int warp = tid >> 5;
    const int lane = tid & 31;
    const int i0   = (bid % 24) * 64;
    const int kv   = bid / 24;
    const int h    = kv * 8 + warp;
    const uint32_t Qs = sbase + 49152 + warp * 2048;

    for (int idx = tid; idx < AROWS * 8; idx += 256) {
        const int r = idx >> 3, c16 = idx & 7;
        const int j = i0 - 128 + r;
        const uint32_t off = (uint32_t)(r * 128) + ((uint32_t)(c16 ^ (r & 7)) << 4);
        if (j >= 0) {
            CP_ASYNC16(Vs + off,
                       (const char*)(v16 + (size_t)j * KV_SIZE + kv * 64) + (c16 << 4));
        } else {
            *reinterpret_cast<uint4*>(asmem + 24576 + off) = make_uint4(0u, 0u, 0u, 0u);
        }
    }
    CP_COMMIT();

    for (int idx = tid; idx < AROWS * 16; idx += 256) {
        const int r = idx >> 4, d2 = idx & 15;
        const int j = i0 - 128 + r;
        float2 y1 = make_float2(0.f, 0.f), y2 = make_float2(0.f, 0.f);
        if (j >= 0) {
            const float* src = qkv + (size_t)j * QKV_COLS + Q_SIZE + kv * 64;
            const float2 x1 = *reinterpret_cast<const float2*>(src + 2 * d2);
            const float2 x2 = *reinterpret_cast<const float2*>(src + 2 * d2 + 32);
            const float2 cc = *reinterpret_cast<const float2*>(rcos + j * 32 + 2 * d2);
            const float2 ss = *reinterpret_cast<const float2*>(rsin + j * 32 + 2 * d2);
            y1.x = x1.x * cc.x - x2.x * ss.x;  y1.y = x1.y * cc.y - x2.y * ss.y;
            y2.x = x2.x * cc.x + x1.x * ss.x;  y2.y = x2.y * cc.y + x1.y * ss.y;
        }
        const int d2b = d2 + 16;
        const uint32_t sw1 = (uint32_t)(r * 128) +
                             ((uint32_t)((d2 >> 2) ^ (r & 7)) << 4) + (d2 & 3) * 4;
        const uint32_t sw2 = (uint32_t)(r * 128) +
                             ((uint32_t)((d2b >> 2) ^ (r & 7)) << 4) + (d2b & 3) * 4;
        *reinterpret_cast<__half2*>(asmem + sw1) = __floats2half2_rn(y1.x, y1.y);
        *reinterpret_cast<__half2*>(asmem + sw2) = __floats2half2_rn(y2.x, y2.y);
    }
    CP_WAIT0();
    __syncthreads();

    const float snk = sinks[h];
    const int r7 = lane & 7;
    const int qq = lane >> 3;
    const int rA = ((qq & 1) << 3) + r7;
    const int cq = qq >> 1;
    const int vrow_l = (lane & 7) + ((lane >> 4) << 3);
    const int vnsel  = (lane >> 3) & 1;

    for (int mt = 0; mt < 4; mt++) {
        const int i_base = i0 + mt * 16;

        __syncwarp();
        for (int e = lane; e < 256; e += 32) {
            const int r = e >> 4, d2 = e & 15;
            const int t = i_base + r;
            const float* src = qkv + (size_t)t * QKV_COLS + h * 64;
            const float2 x1 = *reinterpret_cast<const float2*>(src + 2 * d2);
            const float2 x2 = *reinterpret_cast<const float2*>(src + 2 * d2 + 32);
            const float2 cc = *reinterpret_cast<const float2*>(rcos + t * 32 + 2 * d2);
            const float2 ss = *reinterpret_cast<const float2*>(rsin + t * 32 + 2 * d2);
            float2 y1, y2;
            y1.x = x1.x * cc.x - x2.x * ss.x;  y1.y = x1.y * cc.y - x2.y * ss.y;
            y2.x = x2.x * cc.x + x1.x * ss.x;  y2.y = x2.y * cc.y + x1.y * ss.y;
            const int d2b = d2 + 16;
            const uint32_t sw1 = (uint32_t)(r * 128) +
                                 ((uint32_t)((d2 >> 2) ^ (r & 7)) << 4) + (d2 & 3) * 4;
            const uint32_t sw2 = (uint32_t)(r * 128) +
                                 ((uint32_t)((d2b >> 2) ^ (r & 7)) << 4) + (d2b & 3) * 4;
            *reinterpret_cast<__half2*>(asmem + 49152 + warp * 2048 + sw1) =
                __floats2half2_rn(y1.x, y1.y);
            *reinterpret_cast<__half2*>(asmem + 49152 + warp * 2048 + sw2) =
                __floats2half2_rn(y2.x, y2.y);
        }
        __syncwarp();

        uint32_t aQ[4][4];
        #pragma unroll
        for (int ks = 0; ks < 4; ks++)
            ldsm4(aQ[ks], Qs + (uint32_t)(rA * 128) +
                          ((uint32_t)(((2 * ks + cq) ^ r7)) << 4));

        float m0 = snk, m1 = snk, l0 = 0.f, l1 = 0.f;
        float ofr[8][4];
        #pragma unroll
        for (int dn = 0; dn < 8; dn++)
            #pragma unroll
            for (int c = 0; c < 4; c++) ofr[dn][c] = 0.f;

        const int b_lo = (mt >= 2) ? 1 : 0;
        for (int bb = 0; bb < 5; bb++) {
            const int b = b_lo + bb;

            float sf[4][4];
            #pragma unroll
            for (int nt = 0; nt < 4; nt++)
                #pragma unroll
                for (int c = 0; c < 4; c++) sf[nt][c] = 0.f;

            #pragma unroll
            for (int ks = 0; ks < 4; ks++) {
                uint32_t bk0[4], bk1[4];
                const uint32_t chsw = (uint32_t)(((2 * ks + cq) ^ r7)) << 4;
                ldsm4(bk0, Ks + (uint32_t)((32 * b + rA) * 128) + chsw);
                ldsm4(bk1, Ks + (uint32_t)((32 * b + 16 + rA) * 128) + chsw);
                mma16816(sf[0], aQ[ks], bk0[0], bk0[2]);
                mma16816(sf[1], aQ[ks], bk0[1], bk0[3]);
                mma16816(sf[2], aQ[ks], bk1[0], bk1[2]);
                mma16816(sf[3], aQ[ks], bk1[1], bk1[3]);
            }

            const int jb  = i0 - 128 + 32 * b;
            const int ir0 = i_base + (lane >> 2);
            const int ir1 = ir0 + 8;
            float bm0 = -1e30f, bm1 = -1e30f;
            #pragma unroll
            for (int nt = 0; nt < 4; nt++) {
                const int jc = jb + nt * 8 + 2 * (lane & 3);
                #pragma unroll
                for (int c = 0; c < 2; c++) {
                    const int j = jc + c;
                    const float s0 = sf[nt][c] * ATT_SCALE;
                    const float s1 = sf[nt][c + 2] * ATT_SCALE;
                    const bool ok0 = (j >= 0) && (j <= ir0) && (ir0 - j < 128);
                    const bool ok1 = (j >= 0) && (j <= ir1) && (ir1 - j < 128);
                    sf[nt][c]     = ok0 ? s0 : -1e30f;
                    sf[nt][c + 2] = ok1 ? s1 : -1e30f;
                    bm0 = fmaxf(bm0, sf[nt][c]);
                    bm1 = fmaxf(bm1, sf[nt][c + 2]);
                }
            }
            bm0 = fmaxf(bm0, __shfl_xor_sync(0xFFFFFFFFu, bm0, 1));
            bm0 = fmaxf(bm0, __shfl_xor_sync(0xFFFFFFFFu, bm0, 2));
            bm1 = fmaxf(bm1, __shfl_xor_sync(0xFFFFFFFFu, bm1, 1));
            bm1 = fmaxf(bm1, __shfl_xor_sync(0xFFFFFFFFu, bm1, 2));

            const float nm0 = fmaxf(m0, bm0), nm1 = fmaxf(m1, bm1);
            const float sc0 = __expf(m0 - nm0), sc1 = __expf(m1 - nm1);
            m0 = nm0; m1 = nm1;
            l0 *= sc0; l1 *= sc1;
            #pragma unroll
            for (int dn = 0; dn < 8; dn++) {
                ofr[dn][0] *= sc0; ofr[dn][1] *= sc0;
                ofr[dn][2] *= sc1; ofr[dn][3] *= sc1;
            }

            uint32_t P01[4], P23[4];
            #pragma unroll
            for (int nt = 0; nt < 4; nt++) {
                const float p0 = __expf(sf[nt][0] - m0);
                const float p1 = __expf(sf[nt][1] - m0);
                const float p2 = __expf(sf[nt][2] - m1);
                const float p3 = __expf(sf[nt][3] - m1);
                l0 += p0 + p1;  l1 += p2 + p3;
                const __half2 h01 = __floats2half2_rn(p0, p1);
                const __half2 h23 = __floats2half2_rn(p2, p3);
                P01[nt] = *reinterpret_cast<const uint32_t*>(&h01);
                P23[nt] = *reinterpret_cast<const uint32_t*>(&h23);
            }

            #pragma unroll
            for (int kt = 0; kt < 2; kt++) {
                uint32_t aP[4] = {P01[2 * kt], P23[2 * kt],
                                  P01[2 * kt + 1], P23[2 * kt + 1]};
                const int vr = 32 * b + 16 * kt + vrow_l;
                #pragma unroll
                for (int dp = 0; dp < 4; dp++) {
                    uint32_t bv[4];
                    ldsm4t(bv, Vs + (uint32_t)(vr * 128) +
                               ((uint32_t)(((2 * dp + vnsel) ^ (vr & 7))) << 4));
                    mma16816(ofr[2 * dp],     aP, bv[0], bv[2]);
                    mma16816(ofr[2 * dp + 1], aP, bv[1], bv[3]);
                }
            }
        }

        l0 += __shfl_xor_sync(0xFFFFFFFFu, l0, 1);
        l0 += __shfl_xor_sync(0xFFFFFFFFu, l0, 2);
        l1 += __shfl_xor_sync(0xFFFFFFFFu, l1, 1);
        l1 += __shfl_xor_sync(0xFFFFFFFFu, l1, 2);
        l0 += __expf(snk - m0);
        l1 += __expf(snk - m1);
        const float inv0 = 1.f / l0, inv1 = 1.f / l1;

        const int r0 = i_base + (lane >> 2);
        #pragma unroll
        for (int dn = 0; dn < 8; dn++) {
            const int col = h * 64 + dn * 8 + 2 * (lane & 3);
            const __half2 o0 = __floats2half2_rn(ofr[dn][0] * inv0, ofr[dn][1] * inv0);
            const __half2 o1 = __floats2half2_rn(ofr[dn][2] * inv1, ofr[dn][3] * inv1);
            *reinterpret_cast<__half2*>(out_hi + (size_t)r0 * Q_SIZE + col)       = o0;
            *reinterpret_cast<__half2*>(out_hi + (size_t)(r0 + 8) * Q_SIZE + col) = o1;
        }
    }
}

// ---------------------------------------------------------------------------
// Launch — serial chain, default stream.
// ---------------------------------------------------------------------------
extern "C" void kernel_launch(void* const* d_in, const int* in_sizes, int n_in,
                              void* d_out, int out_size)
{
    const int*   positions = (const int*)  d_in[0];
    const float* hidden    = (const float*)d_in[1];
    const float* W_qkv     = (const float*)d_in[2];
    const float* b_qkv     = (const float*)d_in[3];
    const float* W_o       = (const float*)d_in[4];
    const float* b_o       = (const float*)d_in[5];
    const float* sinks     = (const float*)d_in[6];
    float* out = (float*)d_out;

    float *qkv, *rc, *rs;
    __half *h_hi, *wq_hi, *wo_hi, *a_hi, *v16;
    cudaGetSymbolAddress((void**)&qkv,   g_qkv);
    cudaGetSymbolAddress((void**)&h_hi,  g_h_hi);
    cudaGetSymbolAddress((void**)&wq_hi, g_wq_hi);
    cudaGetSymbolAddress((void**)&wo_hi, g_wo_hi);
    cudaGetSymbolAddress((void**)&a_hi,  g_a_hi);
    cudaGetSymbolAddress((void**)&rc,    g_rcos);
    cudaGetSymbolAddress((void**)&rs,    g_rsin);
    cudaGetSymbolAddress((void**)&v16,   g_v16);

    static bool attr_done = false;
    if (!attr_done) {
        cudaFuncSetAttribute(hgemm1_kernel,
                             cudaFuncAttributeMaxDynamicSharedMemorySize, GEMM_DSMEM);
        cudaFuncSetAttribute(attn_mma_kernel,
                             cudaFuncAttributeMaxDynamicSharedMemorySize, ATTN_DSMEM);
        attr_done = true;
    }

    // 0) preprocessing A (hidden, W_qkv, rope)
    preproc_kernel<<<PP_TOTAL_BLOCKS, 256>>>(hidden, W_qkv, positions,
                                             h_hi, wq_hi, rc, rs);
    // 1) QKV projection (V columns emitted as fp16)
    {
        dim3 grid(QKV_COLS / 128, T_LEN / 128);
        hgemm1_kernel<<<grid, 256, GEMM_DSMEM>>>(h_hi, wq_hi, b_qkv, qkv, v16,
                                                 QKV_COLS, HIDDEN);
    }
    // 2) flash attention + W_o transpose in the free slots
    attn_mma_kernel<<<ATTN_CTAS + WO_MEGA, 256, ATTN_DSMEM>>>(
        qkv, v16, sinks, rc, rs, a_hi, W_o, wo_hi);
    // 3) O projection
    {
        dim3 grid(O_NPAD / 128, T_LEN / 128);
        hgemm1_kernel<<<grid, 256, GEMM_DSMEM>>>(a_hi, wo_hi, b_o, out, nullptr,
                                                 HIDDEN, Q_SIZE);
    }
}

// round 17
// speedup vs baseline: 1.0447x; 1.0243x over previous
#include <cuda_runtime.h>
#include <cuda_fp16.h>
#include <cstdint>
#include <cmath>

// ---------------------------------------------------------------------------
// GPT-OSS attention block on sm_100 (legacy mma.sync path).
// Round 17 (= R16 resubmitted; R16 bench was an infra failure):
// exact R12 base (350.2us) with ONE change — attention Q fragments built
// directly in registers (rope + pack into mma A-frag layout), removing the
// per-task Q smem staging / syncwarps / ldmatrix. Bit-exact vs R12.
// ---------------------------------------------------------------------------

#define T_LEN      1536
#define HIDDEN     2880
#define N_HEADS    64
#define N_KV       8
#define HEAD_DIM   64
#define WINDOW     128
#define Q_SIZE     4096
#define KV_SIZE    512
#define QKV_COLS   5120
#define O_NPAD     2944
#define ATT_SCALE  0.125f

// ---------------- scratch ---------------------------------------------------
__device__ __align__(256) float  g_qkv  [(size_t)T_LEN * QKV_COLS];
__device__ __align__(256) __half g_v16  [(size_t)T_LEN * KV_SIZE];
__device__ __align__(256) __half g_h_hi [(size_t)T_LEN * HIDDEN];
__device__ __align__(256) __half g_wq_hi[(size_t)QKV_COLS * HIDDEN];
__device__ __align__(256) __half g_wo_hi[(size_t)O_NPAD * Q_SIZE];
__device__ __align__(256) __half g_a_hi [(size_t)T_LEN * Q_SIZE];
__device__ __align__(256) float  g_rcos [(size_t)T_LEN * 32];
__device__ __align__(256) float  g_rsin [(size_t)T_LEN * 32];

// ---------------- helpers ---------------------------------------------------
static __device__ __forceinline__ uint32_t smem_u32(const void* p) {
    uint32_t a;
    asm("{ .reg .u64 t; cvta.to.shared.u64 t, %1; cvt.u32.u64 %0, t; }"
        : "=r"(a) : "l"(p));
    return a;
}

#define CP_ASYNC16(dst, src) \
    asm volatile("cp.async.cg.shared.global [%0], [%1], 16;" :: "r"(dst), "l"(src))
#define CP_COMMIT() asm volatile("cp.async.commit_group;")
#define CP_WAIT1()  asm volatile("cp.async.wait_group 1;")
#define CP_WAIT0()  asm volatile("cp.async.wait_group 0;")

static __device__ __forceinline__ void ldsm4(uint32_t* r, uint32_t addr) {
    asm volatile("ldmatrix.sync.aligned.m8n8.x4.shared.b16 {%0,%1,%2,%3}, [%4];"
                 : "=r"(r[0]), "=r"(r[1]), "=r"(r[2]), "=r"(r[3]) : "r"(addr));
}

static __device__ __forceinline__ void ldsm4t(uint32_t* r, uint32_t addr) {
    asm volatile("ldmatrix.sync.aligned.m8n8.x4.trans.shared.b16 {%0,%1,%2,%3}, [%4];"
                 : "=r"(r[0]), "=r"(r[1]), "=r"(r[2]), "=r"(r[3]) : "r"(addr));
}

static __device__ __forceinline__ void mma16816(float* d, const uint32_t* a,
                                                uint32_t b0, uint32_t b1) {
    asm volatile("mma.sync.aligned.m16n8k16.row.col.f32.f16.f16.f32 "
                 "{%0,%1,%2,%3}, {%4,%5,%6,%7}, {%8,%9}, {%0,%1,%2,%3};"
                 : "+f"(d[0]), "+f"(d[1]), "+f"(d[2]), "+f"(d[3])
                 : "r"(a[0]), "r"(a[1]), "r"(a[2]), "r"(a[3]), "r"(b0), "r"(b1));
}

// ---------------------------------------------------------------------------
// 1-pass fp16 HMMA GEMM (identical to R12). V tiles store fp16 to v16.
// ---------------------------------------------------------------------------
#define GS           3
#define TILE_BYTES   16384
#define STAGE_BYTES  (2 * TILE_BYTES)
#define GEMM_DSMEM   (GS * STAGE_BYTES + 1024)
#define V_COL0       4608

static __device__ __forceinline__ void load_chunk(
    uint32_t st,
    const __half* __restrict__ Ah, const __half* __restrict__ Bh,
    int m0, int n0, int kk, int K, int tid)
{
    #pragma unroll
    for (int i = 0; i < 4; i++) {
        int ch  = tid + (i << 8);
        int rw  = ch >> 3;
        int c16 = ch & 7;
        uint32_t off = (uint32_t)(rw << 7) + (uint32_t)(c16 << 4);
        uint32_t sw  = off ^ ((off >> 3) & 0x70);
        const char* sa = (const char*)(Ah + (size_t)(m0 + rw) * K + kk) + (c16 << 4);
        const char* sb = (const char*)(Bh + (size_t)(n0 + rw) * K + kk) + (c16 << 4);
        CP_ASYNC16(st + sw,              sa);
        CP_ASYNC16(st + TILE_BYTES + sw, sb);
    }
}

__global__ __launch_bounds__(256, 2)
void hgemm1_kernel(const __half* __restrict__ A_hi,
                   const __half* __restrict__ B_hi,
                   const float* __restrict__ bias, float* __restrict__ C,
                   __half* __restrict__ v16,
                   int Nreal, int K)
{
    extern __shared__ char dynsmem[];
    const uint32_t tile0 = (smem_u32(dynsmem) + 1023u) & ~1023u;

    const int tid  = threadIdx.x;
    const int wid  = tid >> 5;
    const int lane = tid & 31;
    const int m0   = blockIdx.y * 128;
    const int n0   = blockIdx.x * 128;
    const int wm   = (wid & 1) * 64;
    const int wn   = (wid >> 1) * 32;

    const int r7 = lane & 7;
    const int q  = lane >> 3;
    const int rA = ((q & 1) << 3) + r7;
    const int cq = q >> 1;

    const int nch = K >> 6;

    float acc[4][4][4];
    #pragma unroll
    for (int a = 0; a < 4; a++)
        #pragma unroll
        for (int b = 0; b < 4; b++)
            #pragma unroll
            for (int c = 0; c < 4; c++) acc[a][b][c] = 0.0f;

    #pragma unroll
    for (int c = 0; c < GS - 1; c++) {
        load_chunk(tile0 + c * STAGE_BYTES, A_hi, B_hi, m0, n0, c << 6, K, tid);
        CP_COMMIT();
    }

    int stage_c = 0, stage_p = GS - 1;
    for (int c = 0; c < nch; c++) {
        CP_WAIT1();
        __syncthreads();

        if (c + GS - 1 < nch)
            load_chunk(tile0 + stage_p * STAGE_BYTES, A_hi, B_hi,
                       m0, n0, (c + GS - 1) << 6, K, tid);
        CP_COMMIT();
        if (++stage_p == GS) stage_p = 0;

        const uint32_t aB = tile0 + stage_c * STAGE_BYTES;
        const uint32_t bB = aB + TILE_BYTES;
        if (++stage_c == GS) stage_c = 0;

        #pragma unroll
        for (int ks = 0; ks < 4; ks++) {
            uint32_t afr[4][4], bfr[2][4];
            const uint32_t chsw = (uint32_t)(((ks * 2 + cq) ^ r7) << 4);
            #pragma unroll
            for (int mt = 0; mt < 4; mt++)
                ldsm4(afr[mt], aB + (uint32_t)((wm + mt * 16 + rA) << 7) + chsw);
            #pragma unroll
            for (int ng = 0; ng < 2; ng++)
                ldsm4(bfr[ng], bB + (uint32_t)((wn + ng * 16 + rA) << 7) + chsw);

            #pragma unroll
            for (int mt = 0; mt < 4; mt++)
                #pragma unroll
                for (int nt = 0; nt < 4; nt++) {
                    const int ng = nt >> 1, hl = nt & 1;
                    mma16816(acc[mt][nt], afr[mt], bfr[ng][hl], bfr[ng][hl + 2]);
                }
        }
    }

    const int trow = lane >> 2;
    const int tcol = (lane & 3) * 2;
    const bool vtile = (v16 != nullptr) && (n0 >= V_COL0);
    #pragma unroll
    for (int mt = 0; mt < 4; mt++) {
        #pragma unroll
        for (int nt = 0; nt < 4; nt++) {
            const int col = n0 + wn + nt * 8 + tcol;
            if (col < Nreal) {
                const float2 b2 = *reinterpret_cast<const float2*>(bias + col);
                const int row0 = m0 + wm + mt * 16 + trow;
                float2 o0, o1;
                o0.x = acc[mt][nt][0] + b2.x;  o0.y = acc[mt][nt][1] + b2.y;
                o1.x = acc[mt][nt][2] + b2.x;  o1.y = acc[mt][nt][3] + b2.y;
                if (vtile) {
                    const int vc = col - V_COL0;
                    *reinterpret_cast<__half2*>(v16 + (size_t)row0 * KV_SIZE + vc) =
                        __floats2half2_rn(o0.x, o0.y);
                    *reinterpret_cast<__half2*>(v16 + (size_t)(row0 + 8) * KV_SIZE + vc) =
                        __floats2half2_rn(o1.x, o1.y);
                } else {
                    *reinterpret_cast<float2*>(C + (size_t)row0 * Nreal + col)       = o0;
                    *reinterpret_cast<float2*>(C + (size_t)(row0 + 8) * Nreal + col) = o1;
                }
            }
        }
    }
}

// ---------------------------------------------------------------------------
// Fused preprocessing (identical to R12).
// ---------------------------------------------------------------------------
#define PP_SPLIT_BLOCKS  4320
#define PP_THI1_BLOCKS   7200
#define PP_THI2_BLOCKS   5888
#define PP_ROPE_BLOCKS   192
#define PP_TOTAL_BLOCKS  (PP_SPLIT_BLOCKS + PP_THI1_BLOCKS + PP_THI2_BLOCKS + PP_ROPE_BLOCKS)

__global__ __launch_bounds__(256)
void preproc_kernel(const float* __restrict__ hidden,
                    const float* __restrict__ W_qkv,
                    const float* __restrict__ W_o,
                    const int* __restrict__ positions,
                    __half* __restrict__ h_hi,
                    __half* __restrict__ wq_hi,
                    __half* __restrict__ wo_hi,
                    float* __restrict__ rcos,
                    float* __restrict__ rsin)
{
    __shared__ float tile[64][33];
    const int bid = blockIdx.x;
    const int tid = threadIdx.x;

    if (bid < PP_SPLIT_BLOCKS) {
        const int i = bid * 256 + tid;
        float4 v = reinterpret_cast<const float4*>(hidden)[i];
        reinterpret_cast<__half2*>(h_hi)[2 * i + 0] =
            __halves2half2(__float2half_rn(v.x), __float2half_rn(v.y));
        reinterpret_cast<__half2*>(h_hi)[2 * i + 1] =
            __halves2half2(__float2half_rn(v.z), __float2half_rn(v.w));
        return;
    }

    if (bid < PP_SPLIT_BLOCKS + PP_THI1_BLOCKS + PP_THI2_BLOCKS) {
        const bool j1 = bid < PP_SPLIT_BLOCKS + PP_THI1_BLOCKS;
        const int  b  = j1 ? (bid - PP_SPLIT_BLOCKS)
                           : (bid - PP_SPLIT_BLOCKS - PP_THI1_BLOCKS);
        const int  nx = j1 ? (QKV_COLS / 32) : (O_NPAD / 32);
        const int  K  = j1 ? HIDDEN : Q_SIZE;
        const int  N  = j1 ? QKV_COLS : HIDDEN;
        const float* __restrict__ W = j1 ? W_qkv : W_o;
        __half* __restrict__ dst    = j1 ? wq_hi : wo_hi;

        const int n0 = (b % nx) * 32;
        const int k0 = (b / nx) * 64;

        #pragma unroll
        for (int i = 0; i < 2; i++) {
            const int id = tid + (i << 8);
            const int kr = id >> 3;
            const int c4 = (id & 7) * 4;
            const int n  = n0 + c4;
            float4 v = make_float4(0.f, 0.f, 0.f, 0.f);
            if (n < N)
                v = *reinterpret_cast<const float4*>(W + (size_t)(k0 + kr) * N + n);
            tile[kr][c4 + 0] = v.x;  tile[kr][c4 + 1] = v.y;
            tile[kr][c4 + 2] = v.z;  tile[kr][c4 + 3] = v.w;
        }
        __syncthreads();

        const int nr = tid >> 3;
        const int kc = (tid & 7) * 8;
        __half hb[8];
        #pragma unroll
        for (int x = 0; x < 8; x++)
            hb[x] = __float2half_rn(tile[kc + x][nr]);
        *reinterpret_cast<uint4*>(dst + (size_t)(n0 + nr) * K + k0 + kc) =
            *reinterpret_cast<const uint4*>(hb);
        return;
    }

    // rope table
    {
        const int i = (bid - PP_SPLIT_BLOCKS - PP_THI1_BLOCKS - PP_THI2_BLOCKS) * 256 + tid;
        if (i >= T_LEN * 32) return;
        const int d = i & 31;
        const int t = i >> 5;

        const float p = (float)positions[t];
        const float lnB   = logf(150000.0f);
        const float freq  = expf(lnB * ((float)d / 32.0f));
        const float conc  = 0.1f * logf(32.0f) + 1.0f;
        const float twoPi = 6.283185307179586f;
        const float low   = 32.0f * logf(4096.0f / (32.0f * twoPi)) / lnB;
        const float high  = 32.0f * logf(4096.0f / (1.0f  * twoPi)) / lnB;
        float ramp = ((float)d - low) / (high - low);
        ramp = fminf(fmaxf(ramp, 0.0f), 1.0f);
        const float inv_freq = ramp / (32.0f * freq) + (1.0f - ramp) / freq;

        const float ang = p * inv_freq;
        rcos[i] = cosf(ang) * conc;
        rsin[i] = sinf(ang) * conc;
    }
}

// ---------------------------------------------------------------------------
// Tensor-core flash attention (R12 structure); Q fragments built directly in
// registers from global fp32 + rope table (bit-exact vs smem-staged path).
// ---------------------------------------------------------------------------
#define AROWS       192
#define ATTN_DSMEM  49152     // K 24K + V 24K (Q smem eliminated)

__global__ __launch_bounds__(256, 2)
void attn_mma_kernel(const float* __restrict__ qkv,
                     const __half* __restrict__ v16,
                     const float* __restrict__ sinks,
                     const float* __restrict__ rcos,
                     const float* __restrict__ rsin,
                     __half* __restrict__ out_hi)
{
    extern __shared__ char asmem[];
    const uint32_t sbase = smem_u32(asmem);
    const uint32_t Ks = sbase;
    const uint32_t Vs = sbase + 24576;

    const int tid  = threadIdx.x;
    const int warp = tid >> 5;
    const int lane = tid & 31;
    const int i0   = blockIdx.x * 64;
    const int kv   = blockIdx.y;
    const int h    = kv * 8 + warp;

    // ---- V staging via cp.async ----
    for (int idx = tid; idx < AROWS * 8; idx += 256) {
        const int r = idx >> 3, c16 = idx & 7;
        const int j = i0 - 128 + r;
        const uint32_t off = (uint32_t)(r * 128) + ((uint32_t)(c16 ^ (r & 7)) << 4);
        if (j >= 0) {
            CP_ASYNC16(Vs + off,
                       (const char*)(v16 + (size_t)j * KV_SIZE + kv * 64) + (c16 << 4));
        } else {
            *reinterpret_cast<uint4*>(asmem + 24576 + off) = make_uint4(0u, 0u, 0u, 0u);
        }
    }
    CP_COMMIT();

    // ---- K staging with RoPE ----
    for (int idx = tid; idx < AROWS * 16; idx += 256) {
        const int r = idx >> 4, d2 = idx & 15;
        const int j = i0 - 128 + r;
        float2 y1 = make_float2(0.f, 0.f), y2 = make_float2(0.f, 0.f);
        if (j >= 0) {
            const float* src = qkv + (size_t)j * QKV_COLS + Q_SIZE + kv * 64;
            const float2 x1 = *reinterpret_cast<const float2*>(src + 2 * d2);
            const float2 x2 = *reinterpret_cast<const float2*>(src + 2 * d2 + 32);
            const float2 cc = *reinterpret_cast<const float2*>(rcos + j * 32 + 2 * d2);
            const float2 ss = *reinterpret_cast<const float2*>(rsin + j * 32 + 2 * d2);
            y1.x = x1.x * cc.x - x2.x * ss.x;  y1.y = x1.y * cc.y - x2.y * ss.y;
            y2.x = x2.x * cc.x + x1.x * ss.x;  y2.y = x2.y * cc.y + x1.y * ss.y;
        }
        const int d2b = d2 + 16;
        const uint32_t sw1 = (uint32_t)(r * 128) +
                             ((uint32_t)((d2 >> 2) ^ (r & 7)) << 4) + (d2 & 3) * 4;
        const uint32_t sw2 = (uint32_t)(r * 128) +
                             ((uint32_t)((d2b >> 2) ^ (r & 7)) << 4) + (d2b & 3) * 4;
        *reinterpret_cast<__half2*>(asmem + sw1) = __floats2half2_rn(y1.x, y1.y);
        *reinterpret_cast<__half2*>(asmem + sw2) = __floats2half2_rn(y2.x, y2.y);
    }
    CP_WAIT0();
    __syncthreads();

    const float snk = sinks[h];
    const int r7 = lane & 7;
    const int qq = lane >> 3;
    const int rA = ((qq & 1) << 3) + r7;
    const int cq = qq >> 1;
    const int vrow_l = (lane & 7) + ((lane >> 4) << 3);
    const int vnsel  = (lane >> 3) & 1;
    const int g  = lane >> 2;         // A-frag row-in-8
    const int t4 = lane & 3;          // A-frag col quad

    for (int mt = 0; mt < 4; mt++) {
        const int i_base = i0 + mt * 16;

        // ---- Q fragments: direct register construction (rope from table) ----
        uint32_t aQ[4][4];
        #pragma unroll
        for (int rr = 0; rr < 2; rr++) {
            const int r = i_base + g + rr * 8;
            const float* qp = qkv + (size_t)r * QKV_COLS + h * 64;
            const float* tc = rcos + r * 32;
            const float* ts = rsin + r * 32;
            #pragma unroll
            for (int p = 0; p < 4; p++) {
                const int c = 2 * t4 + 8 * p;        // 0..31
                const float2 xl = *reinterpret_cast<const float2*>(qp + c);
                const float2 xh = *reinterpret_cast<const float2*>(qp + c + 32);
                const float2 cc = *reinterpret_cast<const float2*>(tc + c);
                const float2 ss = *reinterpret_cast<const float2*>(ts + c);
                float2 ylo, yhi;
                ylo.x = xl.x * cc.x - xh.x * ss.x;  ylo.y = xl.y * cc.y - xh.y * ss.y;
                yhi.x = xh.x * cc.x + xl.x * ss.x;  yhi.y = xh.y * cc.y + xl.y * ss.y;
                const __half2 hlo = __floats2half2_rn(ylo.x, ylo.y);
                const __half2 hhi = __floats2half2_rn(yhi.x, yhi.y);
                const int reg = ((p & 1) << 1) + rr;   // 0..3
                aQ[p >> 1][reg]       = *reinterpret_cast<const uint32_t*>(&hlo);
                aQ[(p >> 1) + 2][reg] = *reinterpret_cast<const uint32_t*>(&hhi);
            }
        }

        float m0 = snk, m1 = snk, l0 = 0.f, l1 = 0.f;
        float ofr[8][4];
        #pragma unroll
        for (int dn = 0; dn < 8; dn++)
            #pragma unroll
            for (int c = 0; c < 4; c++) ofr[dn][c] = 0.f;

        const int b_lo = (mt >= 2) ? 1 : 0;
        for (int bb = 0; bb < 5; bb++) {
            const int b = b_lo + bb;

            float sf[4][4];
            #pragma unroll
            for (int nt = 0; nt < 4; nt++)
                #pragma unroll
                for (int c = 0; c < 4; c++) sf[nt][c] = 0.f;

            #pragma unroll
            for (int ks = 0; ks < 4; ks++) {
                uint32_t bk0[4], bk1[4];
                const uint32_t chsw = (uint32_t)(((2 * ks + cq) ^ r7)) << 4;
                ldsm4(bk0, Ks + (uint32_t)((32 * b + rA) * 128) + chsw);
                ldsm4(bk1, Ks + (uint32_t)((32 * b + 16 + rA) * 128) + chsw);
                mma16816(sf[0], aQ[ks], bk0[0], bk0[2]);
                mma16816(sf[1], aQ[ks], bk0[1], bk0[3]);
                mma16816(sf[2], aQ[ks], bk1[0], bk1[2]);
                mma16816(sf[3], aQ[ks], bk1[1], bk1[3]);
            }

            const int jb  = i0 - 128 + 32 * b;
            const int ir0 = i_base + g;
            const int ir1 = ir0 + 8;
            float bm0 = -1e30f, bm1 = -1e30f;
            #pragma unroll
            for (int nt = 0; nt < 4; nt++) {
                const int jc = jb + nt * 8 + 2 * t4;
                #pragma unroll
                for (int c = 0; c < 2; c++) {
                    const int j = jc + c;
                    const float s0 = sf[nt][c] * ATT_SCALE;
                    const float s1 = sf[nt][c + 2] * ATT_SCALE;
                    const bool ok0 = (j >= 0) && (j <= ir0) && (ir0 - j < 128);
                    const bool ok1 = (j >= 0) && (j <= ir1) && (ir1 - j < 128);
                    sf[nt][c]     = ok0 ? s0 : -1e30f;
                    sf[nt][c + 2] = ok1 ? s1 : -1e30f;
                    bm0 = fmaxf(bm0, sf[nt][c]);
                    bm1 = fmaxf(bm1, sf[nt][c + 2]);
                }
            }
            bm0 = fmaxf(bm0, __shfl_xor_sync(0xFFFFFFFFu, bm0, 1));
            bm0 = fmaxf(bm0, __shfl_xor_sync(0xFFFFFFFFu, bm0, 2));
            bm1 = fmaxf(bm1, __shfl_xor_sync(0xFFFFFFFFu, bm1, 1));
            bm1 = fmaxf(bm1, __shfl_xor_sync(0xFFFFFFFFu, bm1, 2));

            const float nm0 = fmaxf(m0, bm0), nm1 = fmaxf(m1, bm1);
            const float sc0 = __expf(m0 - nm0), sc1 = __expf(m1 - nm1);
            m0 = nm0; m1 = nm1;
            l0 *= sc0; l1 *= sc1;
            #pragma unroll
            for (int dn = 0; dn < 8; dn++) {
                ofr[dn][0] *= sc0; ofr[dn][1] *= sc0;
                ofr[dn][2] *= sc1; ofr[dn][3] *= sc1;
            }

            uint32_t P01[4], P23[4];
            #pragma unroll
            for (int nt = 0; nt < 4; nt++) {
                const float p0 = __expf(sf[nt][0] - m0);
                const float p1 = __expf(sf[nt][1] - m0);
                const float p2 = __expf(sf[nt][2] - m1);
                const float p3 = __expf(sf[nt][3] - m1);
                l0 += p0 + p1;  l1 += p2 + p3;
                const __half2 h01 = __floats2half2_rn(p0, p1);
                const __half2 h23 = __floats2half2_rn(p2, p3);
                P01[nt] = *reinterpret_cast<const uint32_t*>(&h01);
                P23[nt] = *reinterpret_cast<const uint32_t*>(&h23);
            }

            #pragma unroll
            for (int kt = 0; kt < 2; kt++) {
                uint32_t aP[4] = {P01[2 * kt], P23[2 * kt],
                                  P01[2 * kt + 1], P23[2 * kt + 1]};
                const int vr = 32 * b + 16 * kt + vrow_l;
                #pragma unroll
                for (int dp = 0; dp < 4; dp++) {
                    uint32_t bv[4];
                    ldsm4t(bv, Vs + (uint32_t)(vr * 128) +
                               ((uint32_t)(((2 * dp + vnsel) ^ (vr & 7))) << 4));
                    mma16816(ofr[2 * dp],     aP, bv[0], bv[2]);
                    mma16816(ofr[2 * dp + 1], aP, bv[1], bv[3]);
                }
            }
        }

        l0 += __shfl_xor_sync(0xFFFFFFFFu, l0, 1);
        l0 += __shfl_xor_sync(0xFFFFFFFFu, l0, 2);
        l1 += __shfl_xor_sync(0xFFFFFFFFu, l1, 1);
        l1 += __shfl_xor_sync(0xFFFFFFFFu, l1, 2);
        l0 += __expf(snk - m0);
        l1 += __expf(snk - m1);
        const float inv0 = 1.f / l0, inv1 = 1.f / l1;

        const int r0 = i_base + g;
        #pragma unroll
        for (int dn = 0; dn < 8; dn++) {
            const int col = h * 64 + dn * 8 + 2 * t4;
            const __half2 o0 = __floats2half2_rn(ofr[dn][0] * inv0, ofr[dn][1] * inv0);
            const __half2 o1 = __floats2half2_rn(ofr[dn][2] * inv1, ofr[dn][3] * inv1);
            *reinterpret_cast<__half2*>(out_hi + (size_t)r0 * Q_SIZE + col)       = o0;
            *reinterpret_cast<__half2*>(out_hi + (size_t)(r0 + 8) * Q_SIZE + col) = o1;
        }
    }
}

// ---------------------------------------------------------------------------
// Launch — serial chain, default stream (R12 ordering).
// ---------------------------------------------------------------------------
extern "C" void kernel_launch(void* const* d_in, const int* in_sizes, int n_in,
                              void* d_out, int out_size)
{
    const int*   positions = (const int*)  d_in[0];
    const float* hidden    = (const float*)d_in[1];
    const float* W_qkv     = (const float*)d_in[2];
    const float* b_qkv     = (const float*)d_in[3];
    const float* W_o       = (const float*)d_in[4];
    const float* b_o       = (const float*)d_in[5];
    const float* sinks     = (const float*)d_in[6];
    float* out = (float*)d_out;

    float *qkv, *rc, *rs;
    __half *h_hi, *wq_hi, *wo_hi, *a_hi, *v16;
    cudaGetSymbolAddress((void**)&qkv,   g_qkv);
    cudaGetSymbolAddress((void**)&h_hi,  g_h_hi);
    cudaGetSymbolAddress((void**)&wq_hi, g_wq_hi);
    cudaGetSymbolAddress((void**)&wo_hi, g_wo_hi);
    cudaGetSymbolAddress((void**)&a_hi,  g_a_hi);
    cudaGetSymbolAddress((void**)&rc,    g_rcos);
    cudaGetSymbolAddress((void**)&rs,    g_rsin);
    cudaGetSymbolAddress((void**)&v16,   g_v16);

    static bool attr_done = false;
    if (!attr_done) {
        cudaFuncSetAttribute(hgemm1_kernel,
                             cudaFuncAttributeMaxDynamicSharedMemorySize, GEMM_DSMEM);
        cudaFuncSetAttribute(attn_mma_kernel,
                             cudaFuncAttributeMaxDynamicSharedMemorySize, ATTN_DSMEM);
        attr_done = true;
    }

    // 0) fused preprocessing
    preproc_kernel<<<PP_TOTAL_BLOCKS, 256>>>(hidden, W_qkv, W_o, positions,
                                             h_hi, wq_hi, wo_hi, rc, rs);
    // 1) QKV projection (V columns emitted as fp16)
    {
        dim3 grid(QKV_COLS / 128, T_LEN / 128);
        hgemm1_kernel<<<grid, 256, GEMM_DSMEM>>>(h_hi, wq_hi, b_qkv, qkv, v16,
                                                 QKV_COLS, HIDDEN);
    }
    // 2) tensor-core flash attention
    {
        dim3 grid(T_LEN / 64, N_KV);
        attn_mma_kernel<<<grid, 256, ATTN_DSMEM>>>(qkv, v16, sinks, rc, rs, a_hi);
    }
    // 3) O projection
    {
        dim3 grid(O_NPAD / 128, T_LEN / 128);
        hgemm1_kernel<<<grid, 256, GEMM_DSMEM>>>(a_hi, wo_hi, b_o, out, nullptr,
                                                 HIDDEN, Q_SIZE);
    }
}